// round 1
// baseline (speedup 1.0000x reference)
#include <cuda_runtime.h>
#include <cuda_bf16.h>

#define N_NODES 100000
#define N_EDGES 3200000
#define F_IN 128
#define NOUT 32

// Scratch (allocation-free: __device__ globals)
__device__ float g_hc[N_NODES * NOUT];     // h @ Wc (scatter source)
__device__ float g_dense[N_NODES * NOUT];  // relu(lin) + relu(lin*lin) branch
__device__ float g_agg1[N_NODES * NOUT];   // scatter destinations (ping-pong)
__device__ float g_agg2[N_NODES * NOUT];

// ---------------------------------------------------------------------------
// K1: layer-1 fat GEMM (K=128). Computes hc = x@Wc1, dense = relu(x@W11+b11)
// + relu((x@W12+b12)*(x@W13+b13)), zeroes agg.
// Warp = 8 nodes, lane = column j of 4 packed matrices (float4 in shared).
// ---------------------------------------------------------------------------
__global__ void k_layer1(const float* __restrict__ x,
                         const float* __restrict__ Wc,
                         const float* __restrict__ Wa, const float* __restrict__ ba,
                         const float* __restrict__ Wm1, const float* __restrict__ bm1,
                         const float* __restrict__ Wm2, const float* __restrict__ bm2,
                         float* __restrict__ hc, float* __restrict__ dense,
                         float* __restrict__ agg)
{
    extern __shared__ float4 W4s[];  // [F_IN][NOUT] packed (Wc, Wa, Wm1, Wm2): 64 KB
    for (int i = threadIdx.x; i < F_IN * NOUT; i += blockDim.x)
        W4s[i] = make_float4(Wc[i], Wa[i], Wm1[i], Wm2[i]);
    __syncthreads();

    const int lane = threadIdx.x & 31;
    const int warp = threadIdx.x >> 5;
    const int node0 = (blockIdx.x * (blockDim.x >> 5) + warp) * 8;
    if (node0 >= N_NODES) return;   // N_NODES % 8 == 0 -> full warps only

    float accC[8], accA[8], accM1[8], accM2[8];
#pragma unroll
    for (int m = 0; m < 8; m++) { accC[m] = accA[m] = accM1[m] = accM2[m] = 0.f; }

    for (int kb = 0; kb < F_IN; kb += 32) {
        float xr[8];
#pragma unroll
        for (int m = 0; m < 8; m++)
            xr[m] = x[(node0 + m) * F_IN + kb + lane];
#pragma unroll
        for (int kk = 0; kk < 32; kk++) {
            float4 w = W4s[(kb + kk) * NOUT + lane];
#pragma unroll
            for (int m = 0; m < 8; m++) {
                float xv = __shfl_sync(0xffffffffu, xr[m], kk);
                accC[m]  = fmaf(xv, w.x, accC[m]);
                accA[m]  = fmaf(xv, w.y, accA[m]);
                accM1[m] = fmaf(xv, w.z, accM1[m]);
                accM2[m] = fmaf(xv, w.w, accM2[m]);
            }
        }
    }

    const float bav = ba[lane], bm1v = bm1[lane], bm2v = bm2[lane];
#pragma unroll
    for (int m = 0; m < 8; m++) {
        int o = (node0 + m) * NOUT + lane;
        hc[o] = accC[m];
        float a = fmaxf(accA[m] + bav, 0.f);
        float p = fmaxf((accM1[m] + bm1v) * (accM2[m] + bm2v), 0.f);
        dense[o] = a + p;
        agg[o] = 0.f;
    }
}

// ---------------------------------------------------------------------------
// Scatter: for each edge e, agg[dst[e]] += hc[src[e]] (32 floats).
// 8 threads per edge, one red.global.add.v4.f32 each (128B line per edge).
// hc and agg are 12.8MB each -> L2 resident.
// ---------------------------------------------------------------------------
__global__ void k_scatter(const int* __restrict__ src, const int* __restrict__ dst,
                          const float* __restrict__ hc, float* __restrict__ agg)
{
    int t = blockIdx.x * blockDim.x + threadIdx.x;
    int e = t >> 3;
    if (e >= N_EDGES) return;
    int c = (t & 7) * 4;
    int s = src[e];
    int d = dst[e];
    float4 v = *reinterpret_cast<const float4*>(hc + s * NOUT + c);
    float* ap = agg + d * NOUT + c;
    asm volatile("red.global.add.v4.f32 [%0], {%1,%2,%3,%4};"
                 :: "l"(ap), "f"(v.x), "f"(v.y), "f"(v.z), "f"(v.w)
                 : "memory");
}

// ---------------------------------------------------------------------------
// K_mid: finish layer i (h = dense + relu(agg + bc_prev)) and run all four
// 32x32 GEMMs of layer i+1. Also zeroes the other agg buffer.
// In-place safe: each warp reads its rows before writing them.
// ---------------------------------------------------------------------------
__global__ void k_mid(const float* __restrict__ dense_in,
                      const float* __restrict__ agg_in,
                      const float* __restrict__ bc_prev,
                      const float* __restrict__ Wc,
                      const float* __restrict__ Wa, const float* __restrict__ ba,
                      const float* __restrict__ Wm1, const float* __restrict__ bm1,
                      const float* __restrict__ Wm2, const float* __restrict__ bm2,
                      float* __restrict__ hc, float* __restrict__ dense_out,
                      float* __restrict__ agg_zero)
{
    __shared__ float4 W4s[NOUT * NOUT];  // 16 KB
    for (int i = threadIdx.x; i < NOUT * NOUT; i += blockDim.x)
        W4s[i] = make_float4(Wc[i], Wa[i], Wm1[i], Wm2[i]);
    __syncthreads();

    const int lane = threadIdx.x & 31;
    const int warp = threadIdx.x >> 5;
    const int node0 = (blockIdx.x * (blockDim.x >> 5) + warp) * 8;
    if (node0 >= N_NODES) return;

    const float bcv = bc_prev[lane];
    float h[8];
#pragma unroll
    for (int m = 0; m < 8; m++) {
        int o = (node0 + m) * NOUT + lane;
        float ag = fmaxf(agg_in[o] + bcv, 0.f);
        h[m] = dense_in[o] + ag;
    }

    float accC[8], accA[8], accM1[8], accM2[8];
#pragma unroll
    for (int m = 0; m < 8; m++) { accC[m] = accA[m] = accM1[m] = accM2[m] = 0.f; }

#pragma unroll
    for (int kk = 0; kk < 32; kk++) {
        float4 w = W4s[kk * NOUT + lane];
#pragma unroll
        for (int m = 0; m < 8; m++) {
            float xv = __shfl_sync(0xffffffffu, h[m], kk);
            accC[m]  = fmaf(xv, w.x, accC[m]);
            accA[m]  = fmaf(xv, w.y, accA[m]);
            accM1[m] = fmaf(xv, w.z, accM1[m]);
            accM2[m] = fmaf(xv, w.w, accM2[m]);
        }
    }

    const float bav = ba[lane], bm1v = bm1[lane], bm2v = bm2[lane];
#pragma unroll
    for (int m = 0; m < 8; m++) {
        int o = (node0 + m) * NOUT + lane;
        hc[o] = accC[m];
        float a = fmaxf(accA[m] + bav, 0.f);
        float p = fmaxf((accM1[m] + bm1v) * (accM2[m] + bm2v), 0.f);
        dense_out[o] = a + p;
        agg_zero[o] = 0.f;
    }
}

// ---------------------------------------------------------------------------
// K_final: h3 = dense + relu(agg + bc3); out = h3 @ W2 + b2. Warp per node.
// ---------------------------------------------------------------------------
__global__ void k_final(const float* __restrict__ dense_in,
                        const float* __restrict__ agg_in,
                        const float* __restrict__ bc,
                        const float* __restrict__ W2, const float* __restrict__ b2,
                        float* __restrict__ out)
{
    int lane = threadIdx.x & 31;
    int node = (blockIdx.x * blockDim.x + threadIdx.x) >> 5;
    if (node >= N_NODES) return;
    int o = node * NOUT + lane;
    float ag = fmaxf(agg_in[o] + bc[lane], 0.f);
    float h = dense_in[o] + ag;
    float v = h * W2[lane];
#pragma unroll
    for (int s = 16; s > 0; s >>= 1)
        v += __shfl_xor_sync(0xffffffffu, v, s);
    if (lane == 0) out[node] = v + b2[0];
}

// ---------------------------------------------------------------------------

extern "C" void kernel_launch(void* const* d_in, const int* in_sizes, int n_in,
                              void* d_out, int out_size)
{
    const float* x   = (const float*)d_in[0];
    const int* ei    = (const int*)d_in[1];
    const int* src   = ei;
    const int* dst   = ei + N_EDGES;
    const float* Wc1 = (const float*)d_in[2];  const float* bc1 = (const float*)d_in[3];
    const float* Wc2 = (const float*)d_in[4];  const float* bc2 = (const float*)d_in[5];
    const float* Wc3 = (const float*)d_in[6];  const float* bc3 = (const float*)d_in[7];
    const float* W11 = (const float*)d_in[8];  const float* b11 = (const float*)d_in[9];
    const float* W12 = (const float*)d_in[10]; const float* b12 = (const float*)d_in[11];
    const float* W13 = (const float*)d_in[12]; const float* b13 = (const float*)d_in[13];
    const float* W21 = (const float*)d_in[14]; const float* b21 = (const float*)d_in[15];
    const float* W22 = (const float*)d_in[16]; const float* b22 = (const float*)d_in[17];
    const float* W23 = (const float*)d_in[18]; const float* b23 = (const float*)d_in[19];
    const float* W31 = (const float*)d_in[20]; const float* b31 = (const float*)d_in[21];
    const float* W32 = (const float*)d_in[22]; const float* b32 = (const float*)d_in[23];
    const float* W33 = (const float*)d_in[24]; const float* b33 = (const float*)d_in[25];
    const float* W2  = (const float*)d_in[26]; const float* b2  = (const float*)d_in[27];
    float* out = (float*)d_out;

    float *hc, *dense, *agg1, *agg2;
    cudaGetSymbolAddress((void**)&hc,    g_hc);
    cudaGetSymbolAddress((void**)&dense, g_dense);
    cudaGetSymbolAddress((void**)&agg1,  g_agg1);
    cudaGetSymbolAddress((void**)&agg2,  g_agg2);

    const int NODE_BLOCKS = (N_NODES / 8 + 7) / 8;   // 8 nodes/warp, 8 warps/block
    const int SCAT_BLOCKS = (N_EDGES * 8) / 256;     // exact
    const int FIN_BLOCKS  = (N_NODES * 32 + 255) / 256;

    static_assert(F_IN * NOUT * sizeof(float4) == 65536, "smem");
    cudaFuncSetAttribute(k_layer1, cudaFuncAttributeMaxDynamicSharedMemorySize, 65536);

    // Layer 1
    k_layer1<<<NODE_BLOCKS, 256, 65536>>>(x, Wc1, W11, b11, W12, b12, W13, b13,
                                          hc, dense, agg1);
    k_scatter<<<SCAT_BLOCKS, 256>>>(src, dst, hc, agg1);
    // Layer 2 (consumes agg1/bc1, produces into agg2)
    k_mid<<<NODE_BLOCKS, 256>>>(dense, agg1, bc1, Wc2, W21, b21, W22, b22, W23, b23,
                                hc, dense, agg2);
    k_scatter<<<SCAT_BLOCKS, 256>>>(src, dst, hc, agg2);
    // Layer 3 (consumes agg2/bc2, produces into agg1)
    k_mid<<<NODE_BLOCKS, 256>>>(dense, agg2, bc2, Wc3, W31, b31, W32, b32, W33, b33,
                                hc, dense, agg1);
    k_scatter<<<SCAT_BLOCKS, 256>>>(src, dst, hc, agg1);
    // Final projection
    k_final<<<FIN_BLOCKS, 256>>>(dense, agg1, bc3, W2, b2, out);
}

// round 2
// speedup vs baseline: 1.1846x; 1.1846x over previous
#include <cuda_runtime.h>
#include <cuda_bf16.h>

#define N_NODES 100000
#define N_EDGES 3200000
#define F_IN 128
#define NOUT 32

#define SCAN_BLOCK 1024
#define SCAN_NBLK ((N_NODES + SCAN_BLOCK - 1) / SCAN_BLOCK)   // 98

// Scratch (allocation-free: __device__ globals)
__device__ float g_hc[N_NODES * NOUT];     // h @ Wc (gather source)
__device__ float g_dense[N_NODES * NOUT];  // relu(lin) + relu(lin*lin) branch
__device__ float g_agg[N_NODES * NOUT];    // gather destination
__device__ int   g_deg[N_NODES];
__device__ int   g_rowstart[N_NODES];
__device__ int   g_cursor[N_NODES];
__device__ int   g_blksum[SCAN_NBLK];
__device__ int   g_csr[N_EDGES];           // src ids grouped by dst

// ---------------------------------------------------------------------------
// CSR build: zero -> hist -> scan(3) -> fill
// ---------------------------------------------------------------------------
__global__ void k_zero_deg(int* __restrict__ deg)
{
    int i = blockIdx.x * blockDim.x + threadIdx.x;
    if (i < N_NODES) deg[i] = 0;
}

__global__ void k_hist(const int* __restrict__ dst, int* __restrict__ deg)
{
    int e = blockIdx.x * blockDim.x + threadIdx.x;
    if (e < N_EDGES) atomicAdd(&deg[dst[e]], 1);
}

// Per-block exclusive scan of deg -> rowstart (partial), block totals -> blksum
__global__ void k_scan1(const int* __restrict__ deg, int* __restrict__ rowstart,
                        int* __restrict__ blksum)
{
    __shared__ int sh[SCAN_BLOCK];
    int i = blockIdx.x * SCAN_BLOCK + threadIdx.x;
    int v = (i < N_NODES) ? deg[i] : 0;
    sh[threadIdx.x] = v;
    __syncthreads();
    // Hillis-Steele inclusive scan in smem
    for (int off = 1; off < SCAN_BLOCK; off <<= 1) {
        int t = (threadIdx.x >= off) ? sh[threadIdx.x - off] : 0;
        __syncthreads();
        sh[threadIdx.x] += t;
        __syncthreads();
    }
    if (i < N_NODES) rowstart[i] = sh[threadIdx.x] - v;   // exclusive
    if (threadIdx.x == SCAN_BLOCK - 1) blksum[blockIdx.x] = sh[threadIdx.x];
}

// Scan the 98 block totals (single block)
__global__ void k_scan2(int* __restrict__ blksum)
{
    __shared__ int sh[128];
    int v = (threadIdx.x < SCAN_NBLK) ? blksum[threadIdx.x] : 0;
    sh[threadIdx.x] = v;
    __syncthreads();
    for (int off = 1; off < 128; off <<= 1) {
        int t = (threadIdx.x >= off) ? sh[threadIdx.x - off] : 0;
        __syncthreads();
        sh[threadIdx.x] += t;
        __syncthreads();
    }
    if (threadIdx.x < SCAN_NBLK) blksum[threadIdx.x] = sh[threadIdx.x] - v; // exclusive
}

__global__ void k_scan3(int* __restrict__ rowstart, const int* __restrict__ blksum,
                        int* __restrict__ cursor)
{
    int i = blockIdx.x * SCAN_BLOCK + threadIdx.x;
    if (i < N_NODES) {
        int r = rowstart[i] + blksum[blockIdx.x];
        rowstart[i] = r;
        cursor[i] = r;
    }
}

__global__ void k_fill(const int* __restrict__ src, const int* __restrict__ dst,
                       int* __restrict__ cursor, int* __restrict__ csr)
{
    int e = blockIdx.x * blockDim.x + threadIdx.x;
    if (e < N_EDGES) {
        int pos = atomicAdd(&cursor[dst[e]], 1);
        csr[pos] = src[e];
    }
}

// ---------------------------------------------------------------------------
// Gather: warp per dst node, lane = column. agg[n][c] = sum_e hc[csr[e]][c].
// Unrolled x4 for MLP; everything L2-resident.
// ---------------------------------------------------------------------------
__global__ void k_gather(const int* __restrict__ csr,
                         const int* __restrict__ rowstart,
                         const int* __restrict__ deg,
                         const float* __restrict__ hc,
                         float* __restrict__ agg)
{
    int lane = threadIdx.x & 31;
    int node = (blockIdx.x * blockDim.x + threadIdx.x) >> 5;
    if (node >= N_NODES) return;
    int start = rowstart[node];
    int d = deg[node];
    float acc = 0.f;
    int i = 0;
    for (; i + 4 <= d; i += 4) {
        int s0 = csr[start + i + 0];
        int s1 = csr[start + i + 1];
        int s2 = csr[start + i + 2];
        int s3 = csr[start + i + 3];
        float v0 = hc[s0 * NOUT + lane];
        float v1 = hc[s1 * NOUT + lane];
        float v2 = hc[s2 * NOUT + lane];
        float v3 = hc[s3 * NOUT + lane];
        acc += (v0 + v1) + (v2 + v3);
    }
    for (; i < d; i++)
        acc += hc[csr[start + i] * NOUT + lane];
    agg[node * NOUT + lane] = acc;
}

// ---------------------------------------------------------------------------
// K1: layer-1 fat GEMM (K=128). hc = x@Wc1, dense = relu(x@W11+b11)
// + relu((x@W12+b12)*(x@W13+b13)).
// ---------------------------------------------------------------------------
__global__ void k_layer1(const float* __restrict__ x,
                         const float* __restrict__ Wc,
                         const float* __restrict__ Wa, const float* __restrict__ ba,
                         const float* __restrict__ Wm1, const float* __restrict__ bm1,
                         const float* __restrict__ Wm2, const float* __restrict__ bm2,
                         float* __restrict__ hc, float* __restrict__ dense)
{
    extern __shared__ float4 W4s[];  // [F_IN][NOUT] packed: 64 KB
    for (int i = threadIdx.x; i < F_IN * NOUT; i += blockDim.x)
        W4s[i] = make_float4(Wc[i], Wa[i], Wm1[i], Wm2[i]);
    __syncthreads();

    const int lane = threadIdx.x & 31;
    const int warp = threadIdx.x >> 5;
    const int node0 = (blockIdx.x * (blockDim.x >> 5) + warp) * 8;
    if (node0 >= N_NODES) return;

    float accC[8], accA[8], accM1[8], accM2[8];
#pragma unroll
    for (int m = 0; m < 8; m++) { accC[m] = accA[m] = accM1[m] = accM2[m] = 0.f; }

    for (int kb = 0; kb < F_IN; kb += 32) {
        float xr[8];
#pragma unroll
        for (int m = 0; m < 8; m++)
            xr[m] = x[(node0 + m) * F_IN + kb + lane];
#pragma unroll
        for (int kk = 0; kk < 32; kk++) {
            float4 w = W4s[(kb + kk) * NOUT + lane];
#pragma unroll
            for (int m = 0; m < 8; m++) {
                float xv = __shfl_sync(0xffffffffu, xr[m], kk);
                accC[m]  = fmaf(xv, w.x, accC[m]);
                accA[m]  = fmaf(xv, w.y, accA[m]);
                accM1[m] = fmaf(xv, w.z, accM1[m]);
                accM2[m] = fmaf(xv, w.w, accM2[m]);
            }
        }
    }

    const float bav = ba[lane], bm1v = bm1[lane], bm2v = bm2[lane];
#pragma unroll
    for (int m = 0; m < 8; m++) {
        int o = (node0 + m) * NOUT + lane;
        hc[o] = accC[m];
        float a = fmaxf(accA[m] + bav, 0.f);
        float p = fmaxf((accM1[m] + bm1v) * (accM2[m] + bm2v), 0.f);
        dense[o] = a + p;
    }
}

// ---------------------------------------------------------------------------
// K_mid: finish layer i (h = dense + relu(agg + bc_prev)), run four 32x32
// GEMMs of layer i+1.
// ---------------------------------------------------------------------------
__global__ void k_mid(const float* __restrict__ dense_in,
                      const float* __restrict__ agg_in,
                      const float* __restrict__ bc_prev,
                      const float* __restrict__ Wc,
                      const float* __restrict__ Wa, const float* __restrict__ ba,
                      const float* __restrict__ Wm1, const float* __restrict__ bm1,
                      const float* __restrict__ Wm2, const float* __restrict__ bm2,
                      float* __restrict__ hc, float* __restrict__ dense_out)
{
    __shared__ float4 W4s[NOUT * NOUT];  // 16 KB
    for (int i = threadIdx.x; i < NOUT * NOUT; i += blockDim.x)
        W4s[i] = make_float4(Wc[i], Wa[i], Wm1[i], Wm2[i]);
    __syncthreads();

    const int lane = threadIdx.x & 31;
    const int warp = threadIdx.x >> 5;
    const int node0 = (blockIdx.x * (blockDim.x >> 5) + warp) * 8;
    if (node0 >= N_NODES) return;

    const float bcv = bc_prev[lane];
    float h[8];
#pragma unroll
    for (int m = 0; m < 8; m++) {
        int o = (node0 + m) * NOUT + lane;
        float ag = fmaxf(agg_in[o] + bcv, 0.f);
        h[m] = dense_in[o] + ag;
    }

    float accC[8], accA[8], accM1[8], accM2[8];
#pragma unroll
    for (int m = 0; m < 8; m++) { accC[m] = accA[m] = accM1[m] = accM2[m] = 0.f; }

#pragma unroll
    for (int kk = 0; kk < 32; kk++) {
        float4 w = W4s[kk * NOUT + lane];
#pragma unroll
        for (int m = 0; m < 8; m++) {
            float xv = __shfl_sync(0xffffffffu, h[m], kk);
            accC[m]  = fmaf(xv, w.x, accC[m]);
            accA[m]  = fmaf(xv, w.y, accA[m]);
            accM1[m] = fmaf(xv, w.z, accM1[m]);
            accM2[m] = fmaf(xv, w.w, accM2[m]);
        }
    }

    const float bav = ba[lane], bm1v = bm1[lane], bm2v = bm2[lane];
#pragma unroll
    for (int m = 0; m < 8; m++) {
        int o = (node0 + m) * NOUT + lane;
        hc[o] = accC[m];
        float a = fmaxf(accA[m] + bav, 0.f);
        float p = fmaxf((accM1[m] + bm1v) * (accM2[m] + bm2v), 0.f);
        dense_out[o] = a + p;
    }
}

// ---------------------------------------------------------------------------
// K_final: h3 = dense + relu(agg + bc3); out = h3 @ W2 + b2. Warp per node.
// ---------------------------------------------------------------------------
__global__ void k_final(const float* __restrict__ dense_in,
                        const float* __restrict__ agg_in,
                        const float* __restrict__ bc,
                        const float* __restrict__ W2, const float* __restrict__ b2,
                        float* __restrict__ out)
{
    int lane = threadIdx.x & 31;
    int node = (blockIdx.x * blockDim.x + threadIdx.x) >> 5;
    if (node >= N_NODES) return;
    int o = node * NOUT + lane;
    float ag = fmaxf(agg_in[o] + bc[lane], 0.f);
    float h = dense_in[o] + ag;
    float v = h * W2[lane];
#pragma unroll
    for (int s = 16; s > 0; s >>= 1)
        v += __shfl_xor_sync(0xffffffffu, v, s);
    if (lane == 0) out[node] = v + b2[0];
}

// ---------------------------------------------------------------------------

extern "C" void kernel_launch(void* const* d_in, const int* in_sizes, int n_in,
                              void* d_out, int out_size)
{
    const float* x   = (const float*)d_in[0];
    const int* ei    = (const int*)d_in[1];
    const int* src   = ei;
    const int* dst   = ei + N_EDGES;
    const float* Wc1 = (const float*)d_in[2];  const float* bc1 = (const float*)d_in[3];
    const float* Wc2 = (const float*)d_in[4];  const float* bc2 = (const float*)d_in[5];
    const float* Wc3 = (const float*)d_in[6];  const float* bc3 = (const float*)d_in[7];
    const float* W11 = (const float*)d_in[8];  const float* b11 = (const float*)d_in[9];
    const float* W12 = (const float*)d_in[10]; const float* b12 = (const float*)d_in[11];
    const float* W13 = (const float*)d_in[12]; const float* b13 = (const float*)d_in[13];
    const float* W21 = (const float*)d_in[14]; const float* b21 = (const float*)d_in[15];
    const float* W22 = (const float*)d_in[16]; const float* b22 = (const float*)d_in[17];
    const float* W23 = (const float*)d_in[18]; const float* b23 = (const float*)d_in[19];
    const float* W31 = (const float*)d_in[20]; const float* b31 = (const float*)d_in[21];
    const float* W32 = (const float*)d_in[22]; const float* b32 = (const float*)d_in[23];
    const float* W33 = (const float*)d_in[24]; const float* b33 = (const float*)d_in[25];
    const float* W2  = (const float*)d_in[26]; const float* b2  = (const float*)d_in[27];
    float* out = (float*)d_out;

    float *hc, *dense, *agg;
    int *deg, *rowstart, *cursor, *blksum, *csr;
    cudaGetSymbolAddress((void**)&hc,       g_hc);
    cudaGetSymbolAddress((void**)&dense,    g_dense);
    cudaGetSymbolAddress((void**)&agg,      g_agg);
    cudaGetSymbolAddress((void**)&deg,      g_deg);
    cudaGetSymbolAddress((void**)&rowstart, g_rowstart);
    cudaGetSymbolAddress((void**)&cursor,   g_cursor);
    cudaGetSymbolAddress((void**)&blksum,   g_blksum);
    cudaGetSymbolAddress((void**)&csr,      g_csr);

    const int NODE_BLOCKS = (N_NODES / 8 + 7) / 8;          // 8 nodes/warp, 8 warps/block
    const int EDGE_BLOCKS = (N_EDGES + 255) / 256;
    const int NVEC_BLOCKS = (N_NODES + 255) / 256;
    const int GATH_BLOCKS = (N_NODES * 32 + 255) / 256;     // warp per node
    const int FIN_BLOCKS  = (N_NODES * 32 + 255) / 256;

    static_assert(F_IN * NOUT * sizeof(float4) == 65536, "smem");
    cudaFuncSetAttribute(k_layer1, cudaFuncAttributeMaxDynamicSharedMemorySize, 65536);

    // --- CSR build (runs concurrently-in-order with layer-1 GEMM's stream) ---
    k_zero_deg<<<NVEC_BLOCKS, 256>>>(deg);
    k_hist<<<EDGE_BLOCKS, 256>>>(dst, deg);
    k_scan1<<<SCAN_NBLK, SCAN_BLOCK>>>(deg, rowstart, blksum);
    k_scan2<<<1, 128>>>(blksum);
    k_scan3<<<SCAN_NBLK, SCAN_BLOCK>>>(rowstart, blksum, cursor);
    k_fill<<<EDGE_BLOCKS, 256>>>(src, dst, cursor, csr);

    // --- Layer 1 ---
    k_layer1<<<NODE_BLOCKS, 256, 65536>>>(x, Wc1, W11, b11, W12, b12, W13, b13,
                                          hc, dense);
    k_gather<<<GATH_BLOCKS, 256>>>(csr, rowstart, deg, hc, agg);
    // --- Layer 2 ---
    k_mid<<<NODE_BLOCKS, 256>>>(dense, agg, bc1, Wc2, W21, b21, W22, b22, W23, b23,
                                hc, dense);
    k_gather<<<GATH_BLOCKS, 256>>>(csr, rowstart, deg, hc, agg);
    // --- Layer 3 ---
    k_mid<<<NODE_BLOCKS, 256>>>(dense, agg, bc2, Wc3, W31, b31, W32, b32, W33, b33,
                                hc, dense);
    k_gather<<<GATH_BLOCKS, 256>>>(csr, rowstart, deg, hc, agg);
    // --- Final projection ---
    k_final<<<FIN_BLOCKS, 256>>>(dense, agg, bc3, W2, b2, out);
}

// round 4
// speedup vs baseline: 1.2662x; 1.0689x over previous
#include <cuda_runtime.h>
#include <cuda_bf16.h>
#include <cstdint>

#define N_NODES 100000
#define N_EDGES 3200000
#define F_IN 128
#define NOUT 32

#define SCAN_BLOCK 1024
#define SCAN_NBLK ((N_NODES + SCAN_BLOCK - 1) / SCAN_BLOCK)   // 98

// Scratch (allocation-free: __device__ globals)
__device__ float g_hc[N_NODES * NOUT];
__device__ float g_dense[N_NODES * NOUT];
__device__ float g_agg[N_NODES * NOUT];
__device__ int   g_deg[N_NODES];
__device__ int   g_rowstart[N_NODES];
__device__ int   g_cursor[N_NODES];
__device__ int   g_blksum[SCAN_NBLK];
__device__ int   g_csr[N_EDGES];

__device__ __forceinline__ uint32_t f2tf32(float f) {
    uint32_t r;
    asm("cvt.rna.tf32.f32 %0, %1;" : "=r"(r) : "f"(f));
    return r;
}

__device__ __forceinline__ void mma_tf32(float& d0, float& d1, float& d2, float& d3,
                                         uint32_t a0, uint32_t a1, uint32_t a2,
                                         uint32_t a3, uint32_t b0, uint32_t b1) {
    asm volatile(
        "mma.sync.aligned.m16n8k8.row.col.f32.tf32.tf32.f32 "
        "{%0,%1,%2,%3}, {%4,%5,%6,%7}, {%8,%9}, {%0,%1,%2,%3};"
        : "+f"(d0), "+f"(d1), "+f"(d2), "+f"(d3)
        : "r"(a0), "r"(a1), "r"(a2), "r"(a3), "r"(b0), "r"(b1));
}

// ===========================================================================
// CSR build: zero -> hist -> scan(3) -> fill
// ===========================================================================
__global__ void k_zero_deg(int* __restrict__ deg)
{
    int i = blockIdx.x * blockDim.x + threadIdx.x;
    if (i < N_NODES) deg[i] = 0;
}

__global__ void k_hist(const int* __restrict__ dst, int* __restrict__ deg)
{
    int e = blockIdx.x * blockDim.x + threadIdx.x;
    if (e < N_EDGES) atomicAdd(&deg[dst[e]], 1);
}

__global__ void k_scan1(const int* __restrict__ deg, int* __restrict__ rowstart,
                        int* __restrict__ blksum)
{
    __shared__ int sh[SCAN_BLOCK];
    int i = blockIdx.x * SCAN_BLOCK + threadIdx.x;
    int v = (i < N_NODES) ? deg[i] : 0;
    sh[threadIdx.x] = v;
    __syncthreads();
    for (int off = 1; off < SCAN_BLOCK; off <<= 1) {
        int t = (threadIdx.x >= off) ? sh[threadIdx.x - off] : 0;
        __syncthreads();
        sh[threadIdx.x] += t;
        __syncthreads();
    }
    if (i < N_NODES) rowstart[i] = sh[threadIdx.x] - v;
    if (threadIdx.x == SCAN_BLOCK - 1) blksum[blockIdx.x] = sh[threadIdx.x];
}

__global__ void k_scan2(int* __restrict__ blksum)
{
    __shared__ int sh[128];
    int v = (threadIdx.x < SCAN_NBLK) ? blksum[threadIdx.x] : 0;
    sh[threadIdx.x] = v;
    __syncthreads();
    for (int off = 1; off < 128; off <<= 1) {
        int t = (threadIdx.x >= off) ? sh[threadIdx.x - off] : 0;
        __syncthreads();
        sh[threadIdx.x] += t;
        __syncthreads();
    }
    if (threadIdx.x < SCAN_NBLK) blksum[threadIdx.x] = sh[threadIdx.x] - v;
}

__global__ void k_scan3(int* __restrict__ rowstart, const int* __restrict__ blksum,
                        int* __restrict__ cursor)
{
    int i = blockIdx.x * SCAN_BLOCK + threadIdx.x;
    if (i < N_NODES) {
        int r = rowstart[i] + blksum[blockIdx.x];
        rowstart[i] = r;
        cursor[i] = r;
    }
}

__global__ void k_fill(const int* __restrict__ src, const int* __restrict__ dst,
                       int* __restrict__ cursor, int* __restrict__ csr)
{
    int e = blockIdx.x * blockDim.x + threadIdx.x;
    if (e < N_EDGES) {
        int pos = atomicAdd(&cursor[dst[e]], 1);
        csr[pos] = src[e];
    }
}

// ===========================================================================
// Gather: warp per dst node, lane = column.
// ===========================================================================
__global__ void k_gather(const int* __restrict__ csr,
                         const int* __restrict__ rowstart,
                         const int* __restrict__ deg,
                         const float* __restrict__ hc,
                         float* __restrict__ agg)
{
    int lane = threadIdx.x & 31;
    int node = (blockIdx.x * blockDim.x + threadIdx.x) >> 5;
    if (node >= N_NODES) return;
    int start = rowstart[node];
    int d = deg[node];
    float acc = 0.f;
    int i = 0;
    for (; i + 4 <= d; i += 4) {
        int s0 = csr[start + i + 0];
        int s1 = csr[start + i + 1];
        int s2 = csr[start + i + 2];
        int s3 = csr[start + i + 3];
        float v0 = hc[s0 * NOUT + lane];
        float v1 = hc[s1 * NOUT + lane];
        float v2 = hc[s2 * NOUT + lane];
        float v3 = hc[s3 * NOUT + lane];
        acc += (v0 + v1) + (v2 + v3);
    }
    for (; i < d; i++)
        acc += hc[csr[start + i] * NOUT + lane];
    agg[node * NOUT + lane] = acc;
}

// Gather fused with final projection.
__global__ void k_gather_final(const int* __restrict__ csr,
                               const int* __restrict__ rowstart,
                               const int* __restrict__ deg,
                               const float* __restrict__ hc,
                               const float* __restrict__ dense_in,
                               const float* __restrict__ bc,
                               const float* __restrict__ W2,
                               const float* __restrict__ b2,
                               float* __restrict__ out)
{
    int lane = threadIdx.x & 31;
    int node = (blockIdx.x * blockDim.x + threadIdx.x) >> 5;
    if (node >= N_NODES) return;
    int start = rowstart[node];
    int d = deg[node];
    float acc = 0.f;
    int i = 0;
    for (; i + 4 <= d; i += 4) {
        int s0 = csr[start + i + 0];
        int s1 = csr[start + i + 1];
        int s2 = csr[start + i + 2];
        int s3 = csr[start + i + 3];
        float v0 = hc[s0 * NOUT + lane];
        float v1 = hc[s1 * NOUT + lane];
        float v2 = hc[s2 * NOUT + lane];
        float v3 = hc[s3 * NOUT + lane];
        acc += (v0 + v1) + (v2 + v3);
    }
    for (; i < d; i++)
        acc += hc[csr[start + i] * NOUT + lane];
    float h = dense_in[node * NOUT + lane] + fmaxf(acc + bc[lane], 0.f);
    float v = h * W2[lane];
#pragma unroll
    for (int s = 16; s > 0; s >>= 1)
        v += __shfl_xor_sync(0xffffffffu, v, s);
    if (lane == 0) out[node] = v + b2[0];
}

// ===========================================================================
// Shared epilogue: from per-warp mma accumulators (16 n-tiles x 4 regs),
// write hc (tiles 0-3) and dense (combining tiles 4-7, 8-11, 12-15).
// ===========================================================================
__device__ __forceinline__ void mma_epilogue(
    const float* acc, int row0, int row1, int tg,
    const float* __restrict__ ba, const float* __restrict__ bm1,
    const float* __restrict__ bm2,
    float* __restrict__ hc, float* __restrict__ dense)
{
    bool v0 = row0 < N_NODES;
    bool v1 = row1 < N_NODES;
#pragma unroll
    for (int j = 0; j < 4; j++) {
        int nb = j * 8 + tg * 2;
        const float* aC  = acc + (j +  0) * 4;
        const float* aA  = acc + (j +  4) * 4;
        const float* aM1 = acc + (j +  8) * 4;
        const float* aM2 = acc + (j + 12) * 4;
        float ba0 = ba[nb],  ba1 = ba[nb + 1];
        float p10 = bm1[nb], p11 = bm1[nb + 1];
        float p20 = bm2[nb], p21 = bm2[nb + 1];
        if (v0) {
            *reinterpret_cast<float2*>(hc + (size_t)row0 * NOUT + nb) =
                make_float2(aC[0], aC[1]);
            float d0 = fmaxf(aA[0] + ba0, 0.f)
                     + fmaxf((aM1[0] + p10) * (aM2[0] + p20), 0.f);
            float d1 = fmaxf(aA[1] + ba1, 0.f)
                     + fmaxf((aM1[1] + p11) * (aM2[1] + p21), 0.f);
            *reinterpret_cast<float2*>(dense + (size_t)row0 * NOUT + nb) =
                make_float2(d0, d1);
        }
        if (v1) {
            *reinterpret_cast<float2*>(hc + (size_t)row1 * NOUT + nb) =
                make_float2(aC[2], aC[3]);
            float d2 = fmaxf(aA[2] + ba0, 0.f)
                     + fmaxf((aM1[2] + p10) * (aM2[2] + p20), 0.f);
            float d3 = fmaxf(aA[3] + ba1, 0.f)
                     + fmaxf((aM1[3] + p11) * (aM2[3] + p21), 0.f);
            *reinterpret_cast<float2*>(dense + (size_t)row1 * NOUT + nb) =
                make_float2(d2, d3);
        }
    }
}

// ===========================================================================
// Layer-1 GEMM via mma.sync tf32. CTA = 256 thr (8 warps) = 128 nodes.
// B packed [K=128][N=128] (Wc|Wa|Wm1|Wm2), smem stride 132 (conflict-free).
// A fragments loaded directly from x (tf32-rounded).
// ===========================================================================
#define BSTRIDE 132

__global__ __launch_bounds__(256)
void k_layer1_mma(const float* __restrict__ x,
                  const float* __restrict__ Wc,
                  const float* __restrict__ Wa, const float* __restrict__ ba,
                  const float* __restrict__ Wm1, const float* __restrict__ bm1,
                  const float* __restrict__ Wm2, const float* __restrict__ bm2,
                  float* __restrict__ hc, float* __restrict__ dense)
{
    extern __shared__ uint32_t Bs[];   // [128][BSTRIDE] tf32 bits: 67584 B
    const int tid = threadIdx.x;
    const float* Ws[4] = { Wc, Wa, Wm1, Wm2 };
    for (int idx = tid; idx < F_IN * 128; idx += 256) {
        int k = idx >> 7;
        int n = idx & 127;
        Bs[k * BSTRIDE + n] = f2tf32(Ws[n >> 5][k * NOUT + (n & 31)]);
    }
    __syncthreads();

    const int w = tid >> 5;
    const int lane = tid & 31;
    const int g = lane >> 2;       // group id (row within tile)
    const int tg = lane & 3;       // thread in group
    const int node0 = blockIdx.x * 128 + w * 16;
    const int row0 = node0 + g;
    const int row1 = row0 + 8;
    // clamp loads for tail CTA (outputs guarded in epilogue)
    const float* xr0 = x + (size_t)((row0 < N_NODES) ? row0 : N_NODES - 1) * F_IN;
    const float* xr1 = x + (size_t)((row1 < N_NODES) ? row1 : N_NODES - 1) * F_IN;

    float acc[64];
#pragma unroll
    for (int i = 0; i < 64; i++) acc[i] = 0.f;

#pragma unroll
    for (int kb = 0; kb < F_IN; kb += 8) {
        uint32_t a0 = f2tf32(xr0[kb + tg]);
        uint32_t a1 = f2tf32(xr1[kb + tg]);
        uint32_t a2 = f2tf32(xr0[kb + tg + 4]);
        uint32_t a3 = f2tf32(xr1[kb + tg + 4]);
        const uint32_t* Bk0 = Bs + (kb + tg) * BSTRIDE;
        const uint32_t* Bk1 = Bs + (kb + tg + 4) * BSTRIDE;
#pragma unroll
        for (int j = 0; j < 16; j++) {
            uint32_t b0 = Bk0[j * 8 + g];
            uint32_t b1 = Bk1[j * 8 + g];
            mma_tf32(acc[j * 4 + 0], acc[j * 4 + 1], acc[j * 4 + 2], acc[j * 4 + 3],
                     a0, a1, a2, a3, b0, b1);
        }
    }

    mma_epilogue(acc, row0, row1, tg, ba, bm1, bm2, hc, dense);
}

// ===========================================================================
// K_mid GEMM via mma.sync tf32 (K=32). h staged in smem (stride 36).
// ===========================================================================
#define HSTRIDE 36

__global__ __launch_bounds__(256)
void k_mid_mma(const float* __restrict__ dense_in,
               const float* __restrict__ agg_in,
               const float* __restrict__ bc_prev,
               const float* __restrict__ Wc,
               const float* __restrict__ Wa, const float* __restrict__ ba,
               const float* __restrict__ Wm1, const float* __restrict__ bm1,
               const float* __restrict__ Wm2, const float* __restrict__ bm2,
               float* __restrict__ hc, float* __restrict__ dense_out)
{
    __shared__ uint32_t Bs[NOUT * BSTRIDE];     // 32x128 packed weights: 16.9 KB
    __shared__ uint32_t Hs[128 * HSTRIDE];      // 128x32 h tile: 18.4 KB
    const int tid = threadIdx.x;
    const int node0b = blockIdx.x * 128;

    const float* Ws[4] = { Wc, Wa, Wm1, Wm2 };
    for (int idx = tid; idx < NOUT * 128; idx += 256) {
        int k = idx >> 7;
        int n = idx & 127;
        Bs[k * BSTRIDE + n] = f2tf32(Ws[n >> 5][k * NOUT + (n & 31)]);
    }
    // h tile: 128 nodes x 32 cols
#pragma unroll
    for (int i = 0; i < 16; i++) {
        int idx = i * 256 + tid;
        int r = idx >> 5;
        int c = idx & 31;
        int node = node0b + r;
        float h = 0.f;
        if (node < N_NODES) {
            size_t o = (size_t)node * NOUT + c;
            h = dense_in[o] + fmaxf(agg_in[o] + bc_prev[c], 0.f);
        }
        Hs[r * HSTRIDE + c] = f2tf32(h);
    }
    __syncthreads();

    const int w = tid >> 5;
    const int lane = tid & 31;
    const int g = lane >> 2;
    const int tg = lane & 3;
    const int rloc0 = w * 16 + g;
    const int rloc1 = rloc0 + 8;
    const int row0 = node0b + rloc0;
    const int row1 = node0b + rloc1;

    float acc[64];
#pragma unroll
    for (int i = 0; i < 64; i++) acc[i] = 0.f;

#pragma unroll
    for (int kb = 0; kb < NOUT; kb += 8) {
        uint32_t a0 = Hs[rloc0 * HSTRIDE + kb + tg];
        uint32_t a1 = Hs[rloc1 * HSTRIDE + kb + tg];
        uint32_t a2 = Hs[rloc0 * HSTRIDE + kb + tg + 4];
        uint32_t a3 = Hs[rloc1 * HSTRIDE + kb + tg + 4];
        const uint32_t* Bk0 = Bs + (kb + tg) * BSTRIDE;
        const uint32_t* Bk1 = Bs + (kb + tg + 4) * BSTRIDE;
#pragma unroll
        for (int j = 0; j < 16; j++) {
            uint32_t b0 = Bk0[j * 8 + g];
            uint32_t b1 = Bk1[j * 8 + g];
            mma_tf32(acc[j * 4 + 0], acc[j * 4 + 1], acc[j * 4 + 2], acc[j * 4 + 3],
                     a0, a1, a2, a3, b0, b1);
        }
    }

    mma_epilogue(acc, row0, row1, tg, ba, bm1, bm2, hc, dense_out);
}

// ===========================================================================

extern "C" void kernel_launch(void* const* d_in, const int* in_sizes, int n_in,
                              void* d_out, int out_size)
{
    const float* x   = (const float*)d_in[0];
    const int* ei    = (const int*)d_in[1];
    const int* src   = ei;
    const int* dst   = ei + N_EDGES;
    const float* Wc1 = (const float*)d_in[2];  const float* bc1 = (const float*)d_in[3];
    const float* Wc2 = (const float*)d_in[4];  const float* bc2 = (const float*)d_in[5];
    const float* Wc3 = (const float*)d_in[6];  const float* bc3 = (const float*)d_in[7];
    const float* W11 = (const float*)d_in[8];  const float* b11 = (const float*)d_in[9];
    const float* W12 = (const float*)d_in[10]; const float* b12 = (const float*)d_in[11];
    const float* W13 = (const float*)d_in[12]; const float* b13 = (const float*)d_in[13];
    const float* W21 = (const float*)d_in[14]; const float* b21 = (const float*)d_in[15];
    const float* W22 = (const float*)d_in[16]; const float* b22 = (const float*)d_in[17];
    const float* W23 = (const float*)d_in[18]; const float* b23 = (const float*)d_in[19];
    const float* W31 = (const float*)d_in[20]; const float* b31 = (const float*)d_in[21];
    const float* W32 = (const float*)d_in[22]; const float* b32 = (const float*)d_in[23];
    const float* W33 = (const float*)d_in[24]; const float* b33 = (const float*)d_in[25];
    const float* W2  = (const float*)d_in[26]; const float* b2  = (const float*)d_in[27];
    float* out = (float*)d_out;

    float *hc, *dense, *agg;
    int *deg, *rowstart, *cursor, *blksum, *csr;
    cudaGetSymbolAddress((void**)&hc,       g_hc);
    cudaGetSymbolAddress((void**)&dense,    g_dense);
    cudaGetSymbolAddress((void**)&agg,      g_agg);
    cudaGetSymbolAddress((void**)&deg,      g_deg);
    cudaGetSymbolAddress((void**)&rowstart, g_rowstart);
    cudaGetSymbolAddress((void**)&cursor,   g_cursor);
    cudaGetSymbolAddress((void**)&blksum,   g_blksum);
    cudaGetSymbolAddress((void**)&csr,      g_csr);

    const int EDGE_BLOCKS = (N_EDGES + 255) / 256;
    const int NVEC_BLOCKS = (N_NODES + 255) / 256;
    const int GATH_BLOCKS = (N_NODES * 32 + 255) / 256;
    const int MMA_BLOCKS  = (N_NODES + 127) / 128;   // 782

    const int L1_SMEM = F_IN * BSTRIDE * 4;          // 67584 B
    cudaFuncSetAttribute(k_layer1_mma, cudaFuncAttributeMaxDynamicSharedMemorySize,
                         L1_SMEM);

    // --- CSR build ---
    k_zero_deg<<<NVEC_BLOCKS, 256>>>(deg);
    k_hist<<<EDGE_BLOCKS, 256>>>(dst, deg);
    k_scan1<<<SCAN_NBLK, SCAN_BLOCK>>>(deg, rowstart, blksum);
    k_scan2<<<1, 128>>>(blksum);
    k_scan3<<<SCAN_NBLK, SCAN_BLOCK>>>(rowstart, blksum, cursor);
    k_fill<<<EDGE_BLOCKS, 256>>>(src, dst, cursor, csr);

    // --- Layer 1 (mma.sync tf32) ---
    k_layer1_mma<<<MMA_BLOCKS, 256, L1_SMEM>>>(x, Wc1, W11, b11, W12, b12,
                                               W13, b13, hc, dense);
    k_gather<<<GATH_BLOCKS, 256>>>(csr, rowstart, deg, hc, agg);
    // --- Layer 2 ---
    k_mid_mma<<<MMA_BLOCKS, 256>>>(dense, agg, bc1, Wc2, W21, b21, W22, b22,
                                   W23, b23, hc, dense);
    k_gather<<<GATH_BLOCKS, 256>>>(csr, rowstart, deg, hc, agg);
    // --- Layer 3 ---
    k_mid_mma<<<MMA_BLOCKS, 256>>>(dense, agg, bc2, Wc3, W31, b31, W32, b32,
                                   W33, b33, hc, dense);
    // --- Gather 3 fused with final projection ---
    k_gather_final<<<GATH_BLOCKS, 256>>>(csr, rowstart, deg, hc, dense, bc3, W2, b2,
                                         out);
}

// round 5
// speedup vs baseline: 1.3295x; 1.0500x over previous
#include <cuda_runtime.h>
#include <cuda_bf16.h>
#include <cstdint>

#define N_NODES 100000
#define N_EDGES 3200000
#define F_IN 128
#define NOUT 32

#define SCAN_BLOCK 1024
#define SCAN_NBLK ((N_NODES + SCAN_BLOCK - 1) / SCAN_BLOCK)   // 98

// Conflict-free smem strides: stride mod 32 == 8 -> fragment LDS hits 32 banks
#define BSTRIDE 136
#define HSTRIDE 40

// Scratch (allocation-free: __device__ globals)
__device__ float g_hc[N_NODES * NOUT];
__device__ float g_dense[N_NODES * NOUT];
__device__ float g_agg[N_NODES * NOUT];
__device__ int   g_deg[N_NODES];
__device__ int   g_rowstart[N_NODES];
__device__ int   g_cursor[N_NODES];
__device__ int   g_blksum[SCAN_NBLK];
__device__ int   g_csr[N_EDGES];

__device__ __forceinline__ uint32_t f2tf32(float f) {
    uint32_t r;
    asm("cvt.rna.tf32.f32 %0, %1;" : "=r"(r) : "f"(f));
    return r;
}

__device__ __forceinline__ void mma_tf32(float& d0, float& d1, float& d2, float& d3,
                                         uint32_t a0, uint32_t a1, uint32_t a2,
                                         uint32_t a3, uint32_t b0, uint32_t b1) {
    asm volatile(
        "mma.sync.aligned.m16n8k8.row.col.f32.tf32.tf32.f32 "
        "{%0,%1,%2,%3}, {%4,%5,%6,%7}, {%8,%9}, {%0,%1,%2,%3};"
        : "+f"(d0), "+f"(d1), "+f"(d2), "+f"(d3)
        : "r"(a0), "r"(a1), "r"(a2), "r"(a3), "r"(b0), "r"(b1));
}

// ===========================================================================
// CSR build: zero -> hist -> scan(3) -> fill
// ===========================================================================
__global__ void k_zero_deg(int* __restrict__ deg)
{
    int i = blockIdx.x * blockDim.x + threadIdx.x;
    if (i < N_NODES) deg[i] = 0;
}

__global__ void k_hist(const int* __restrict__ dst, int* __restrict__ deg)
{
    int e = blockIdx.x * blockDim.x + threadIdx.x;
    if (e < N_EDGES) atomicAdd(&deg[dst[e]], 1);
}

__global__ void k_scan1(const int* __restrict__ deg, int* __restrict__ rowstart,
                        int* __restrict__ blksum)
{
    __shared__ int sh[SCAN_BLOCK];
    int i = blockIdx.x * SCAN_BLOCK + threadIdx.x;
    int v = (i < N_NODES) ? deg[i] : 0;
    sh[threadIdx.x] = v;
    __syncthreads();
    for (int off = 1; off < SCAN_BLOCK; off <<= 1) {
        int t = (threadIdx.x >= off) ? sh[threadIdx.x - off] : 0;
        __syncthreads();
        sh[threadIdx.x] += t;
        __syncthreads();
    }
    if (i < N_NODES) rowstart[i] = sh[threadIdx.x] - v;
    if (threadIdx.x == SCAN_BLOCK - 1) blksum[blockIdx.x] = sh[threadIdx.x];
}

__global__ void k_scan2(int* __restrict__ blksum)
{
    __shared__ int sh[128];
    int v = (threadIdx.x < SCAN_NBLK) ? blksum[threadIdx.x] : 0;
    sh[threadIdx.x] = v;
    __syncthreads();
    for (int off = 1; off < 128; off <<= 1) {
        int t = (threadIdx.x >= off) ? sh[threadIdx.x - off] : 0;
        __syncthreads();
        sh[threadIdx.x] += t;
        __syncthreads();
    }
    if (threadIdx.x < SCAN_NBLK) blksum[threadIdx.x] = sh[threadIdx.x] - v;
}

__global__ void k_scan3(int* __restrict__ rowstart, const int* __restrict__ blksum,
                        int* __restrict__ cursor)
{
    int i = blockIdx.x * SCAN_BLOCK + threadIdx.x;
    if (i < N_NODES) {
        int r = rowstart[i] + blksum[blockIdx.x];
        rowstart[i] = r;
        cursor[i] = r;
    }
}

__global__ void k_fill(const int* __restrict__ src, const int* __restrict__ dst,
                       int* __restrict__ cursor, int* __restrict__ csr)
{
    int e = blockIdx.x * blockDim.x + threadIdx.x;
    if (e < N_EDGES) {
        int pos = atomicAdd(&cursor[dst[e]], 1);
        csr[pos] = src[e];
    }
}

// ===========================================================================
// Gather: warp per dst node, lane = column.
// ===========================================================================
__global__ void k_gather(const int* __restrict__ csr,
                         const int* __restrict__ rowstart,
                         const int* __restrict__ deg,
                         const float* __restrict__ hc,
                         float* __restrict__ agg)
{
    int lane = threadIdx.x & 31;
    int node = (blockIdx.x * blockDim.x + threadIdx.x) >> 5;
    if (node >= N_NODES) return;
    int start = rowstart[node];
    int d = deg[node];
    float acc = 0.f;
    int i = 0;
    for (; i + 4 <= d; i += 4) {
        int s0 = csr[start + i + 0];
        int s1 = csr[start + i + 1];
        int s2 = csr[start + i + 2];
        int s3 = csr[start + i + 3];
        float v0 = hc[s0 * NOUT + lane];
        float v1 = hc[s1 * NOUT + lane];
        float v2 = hc[s2 * NOUT + lane];
        float v3 = hc[s3 * NOUT + lane];
        acc += (v0 + v1) + (v2 + v3);
    }
    for (; i < d; i++)
        acc += hc[csr[start + i] * NOUT + lane];
    agg[node * NOUT + lane] = acc;
}

// Gather fused with final projection.
__global__ void k_gather_final(const int* __restrict__ csr,
                               const int* __restrict__ rowstart,
                               const int* __restrict__ deg,
                               const float* __restrict__ hc,
                               const float* __restrict__ dense_in,
                               const float* __restrict__ bc,
                               const float* __restrict__ W2,
                               const float* __restrict__ b2,
                               float* __restrict__ out)
{
    int lane = threadIdx.x & 31;
    int node = (blockIdx.x * blockDim.x + threadIdx.x) >> 5;
    if (node >= N_NODES) return;
    int start = rowstart[node];
    int d = deg[node];
    float acc = 0.f;
    int i = 0;
    for (; i + 4 <= d; i += 4) {
        int s0 = csr[start + i + 0];
        int s1 = csr[start + i + 1];
        int s2 = csr[start + i + 2];
        int s3 = csr[start + i + 3];
        float v0 = hc[s0 * NOUT + lane];
        float v1 = hc[s1 * NOUT + lane];
        float v2 = hc[s2 * NOUT + lane];
        float v3 = hc[s3 * NOUT + lane];
        acc += (v0 + v1) + (v2 + v3);
    }
    for (; i < d; i++)
        acc += hc[csr[start + i] * NOUT + lane];
    float h = dense_in[node * NOUT + lane] + fmaxf(acc + bc[lane], 0.f);
    float v = h * W2[lane];
#pragma unroll
    for (int s = 16; s > 0; s >>= 1)
        v += __shfl_xor_sync(0xffffffffu, v, s);
    if (lane == 0) out[node] = v + b2[0];
}

// ===========================================================================
// Shared epilogue for the mma kernels.
// ===========================================================================
__device__ __forceinline__ void mma_epilogue(
    const float* acc, int row0, int row1, int tg,
    const float* __restrict__ ba, const float* __restrict__ bm1,
    const float* __restrict__ bm2,
    float* __restrict__ hc, float* __restrict__ dense)
{
    bool v0 = row0 < N_NODES;
    bool v1 = row1 < N_NODES;
#pragma unroll
    for (int j = 0; j < 4; j++) {
        int nb = j * 8 + tg * 2;
        const float* aC  = acc + (j +  0) * 4;
        const float* aA  = acc + (j +  4) * 4;
        const float* aM1 = acc + (j +  8) * 4;
        const float* aM2 = acc + (j + 12) * 4;
        float ba0 = ba[nb],  ba1 = ba[nb + 1];
        float p10 = bm1[nb], p11 = bm1[nb + 1];
        float p20 = bm2[nb], p21 = bm2[nb + 1];
        if (v0) {
            *reinterpret_cast<float2*>(hc + (size_t)row0 * NOUT + nb) =
                make_float2(aC[0], aC[1]);
            float d0 = fmaxf(aA[0] + ba0, 0.f)
                     + fmaxf((aM1[0] + p10) * (aM2[0] + p20), 0.f);
            float d1 = fmaxf(aA[1] + ba1, 0.f)
                     + fmaxf((aM1[1] + p11) * (aM2[1] + p21), 0.f);
            *reinterpret_cast<float2*>(dense + (size_t)row0 * NOUT + nb) =
                make_float2(d0, d1);
        }
        if (v1) {
            *reinterpret_cast<float2*>(hc + (size_t)row1 * NOUT + nb) =
                make_float2(aC[2], aC[3]);
            float d2 = fmaxf(aA[2] + ba0, 0.f)
                     + fmaxf((aM1[2] + p10) * (aM2[2] + p20), 0.f);
            float d3 = fmaxf(aA[3] + ba1, 0.f)
                     + fmaxf((aM1[3] + p11) * (aM2[3] + p21), 0.f);
            *reinterpret_cast<float2*>(dense + (size_t)row1 * NOUT + nb) =
                make_float2(d2, d3);
        }
    }
}

// ===========================================================================
// Layer-1 GEMM via mma.sync tf32. CTA = 256 thr (8 warps) = 128 nodes.
// ===========================================================================
__global__ __launch_bounds__(256)
void k_layer1_mma(const float* __restrict__ x,
                  const float* __restrict__ Wc,
                  const float* __restrict__ Wa, const float* __restrict__ ba,
                  const float* __restrict__ Wm1, const float* __restrict__ bm1,
                  const float* __restrict__ Wm2, const float* __restrict__ bm2,
                  float* __restrict__ hc, float* __restrict__ dense)
{
    extern __shared__ uint32_t Bs[];   // [128][BSTRIDE] tf32 bits
    const int tid = threadIdx.x;
    const float* Ws[4] = { Wc, Wa, Wm1, Wm2 };
    for (int idx = tid; idx < F_IN * 128; idx += 256) {
        int k = idx >> 7;
        int n = idx & 127;
        Bs[k * BSTRIDE + n] = f2tf32(Ws[n >> 5][k * NOUT + (n & 31)]);
    }
    __syncthreads();

    const int w = tid >> 5;
    const int lane = tid & 31;
    const int g = lane >> 2;
    const int tg = lane & 3;
    const int node0 = blockIdx.x * 128 + w * 16;
    const int row0 = node0 + g;
    const int row1 = row0 + 8;
    const float* xr0 = x + (size_t)((row0 < N_NODES) ? row0 : N_NODES - 1) * F_IN;
    const float* xr1 = x + (size_t)((row1 < N_NODES) ? row1 : N_NODES - 1) * F_IN;

    float acc[64];
#pragma unroll
    for (int i = 0; i < 64; i++) acc[i] = 0.f;

#pragma unroll
    for (int kb = 0; kb < F_IN; kb += 8) {
        uint32_t a0 = f2tf32(xr0[kb + tg]);
        uint32_t a1 = f2tf32(xr1[kb + tg]);
        uint32_t a2 = f2tf32(xr0[kb + tg + 4]);
        uint32_t a3 = f2tf32(xr1[kb + tg + 4]);
        const uint32_t* Bk0 = Bs + (kb + tg) * BSTRIDE;
        const uint32_t* Bk1 = Bs + (kb + tg + 4) * BSTRIDE;
#pragma unroll
        for (int j = 0; j < 16; j++) {
            uint32_t b0 = Bk0[j * 8 + g];
            uint32_t b1 = Bk1[j * 8 + g];
            mma_tf32(acc[j * 4 + 0], acc[j * 4 + 1], acc[j * 4 + 2], acc[j * 4 + 3],
                     a0, a1, a2, a3, b0, b1);
        }
    }

    mma_epilogue(acc, row0, row1, tg, ba, bm1, bm2, hc, dense);
}

// ===========================================================================
// K_mid GEMM via mma.sync tf32 (K=32). h staged in smem.
// ===========================================================================
__global__ __launch_bounds__(256)
void k_mid_mma(const float* __restrict__ dense_in,
               const float* __restrict__ agg_in,
               const float* __restrict__ bc_prev,
               const float* __restrict__ Wc,
               const float* __restrict__ Wa, const float* __restrict__ ba,
               const float* __restrict__ Wm1, const float* __restrict__ bm1,
               const float* __restrict__ Wm2, const float* __restrict__ bm2,
               float* __restrict__ hc, float* __restrict__ dense_out)
{
    __shared__ uint32_t Bs[NOUT * BSTRIDE];
    __shared__ uint32_t Hs[128 * HSTRIDE];
    const int tid = threadIdx.x;
    const int node0b = blockIdx.x * 128;

    const float* Ws[4] = { Wc, Wa, Wm1, Wm2 };
    for (int idx = tid; idx < NOUT * 128; idx += 256) {
        int k = idx >> 7;
        int n = idx & 127;
        Bs[k * BSTRIDE + n] = f2tf32(Ws[n >> 5][k * NOUT + (n & 31)]);
    }
#pragma unroll
    for (int i = 0; i < 16; i++) {
        int idx = i * 256 + tid;
        int r = idx >> 5;
        int c = idx & 31;
        int node = node0b + r;
        float h = 0.f;
        if (node < N_NODES) {
            size_t o = (size_t)node * NOUT + c;
            h = dense_in[o] + fmaxf(agg_in[o] + bc_prev[c], 0.f);
        }
        Hs[r * HSTRIDE + c] = f2tf32(h);
    }
    __syncthreads();

    const int w = tid >> 5;
    const int lane = tid & 31;
    const int g = lane >> 2;
    const int tg = lane & 3;
    const int rloc0 = w * 16 + g;
    const int rloc1 = rloc0 + 8;
    const int row0 = node0b + rloc0;
    const int row1 = node0b + rloc1;

    float acc[64];
#pragma unroll
    for (int i = 0; i < 64; i++) acc[i] = 0.f;

#pragma unroll
    for (int kb = 0; kb < NOUT; kb += 8) {
        uint32_t a0 = Hs[rloc0 * HSTRIDE + kb + tg];
        uint32_t a1 = Hs[rloc1 * HSTRIDE + kb + tg];
        uint32_t a2 = Hs[rloc0 * HSTRIDE + kb + tg + 4];
        uint32_t a3 = Hs[rloc1 * HSTRIDE + kb + tg + 4];
        const uint32_t* Bk0 = Bs + (kb + tg) * BSTRIDE;
        const uint32_t* Bk1 = Bs + (kb + tg + 4) * BSTRIDE;
#pragma unroll
        for (int j = 0; j < 16; j++) {
            uint32_t b0 = Bk0[j * 8 + g];
            uint32_t b1 = Bk1[j * 8 + g];
            mma_tf32(acc[j * 4 + 0], acc[j * 4 + 1], acc[j * 4 + 2], acc[j * 4 + 3],
                     a0, a1, a2, a3, b0, b1);
        }
    }

    mma_epilogue(acc, row0, row1, tg, ba, bm1, bm2, hc, dense_out);
}

// ===========================================================================

extern "C" void kernel_launch(void* const* d_in, const int* in_sizes, int n_in,
                              void* d_out, int out_size)
{
    const float* x   = (const float*)d_in[0];
    const int* ei    = (const int*)d_in[1];
    const int* src   = ei;
    const int* dst   = ei + N_EDGES;
    const float* Wc1 = (const float*)d_in[2];  const float* bc1 = (const float*)d_in[3];
    const float* Wc2 = (const float*)d_in[4];  const float* bc2 = (const float*)d_in[5];
    const float* Wc3 = (const float*)d_in[6];  const float* bc3 = (const float*)d_in[7];
    const float* W11 = (const float*)d_in[8];  const float* b11 = (const float*)d_in[9];
    const float* W12 = (const float*)d_in[10]; const float* b12 = (const float*)d_in[11];
    const float* W13 = (const float*)d_in[12]; const float* b13 = (const float*)d_in[13];
    const float* W21 = (const float*)d_in[14]; const float* b21 = (const float*)d_in[15];
    const float* W22 = (const float*)d_in[16]; const float* b22 = (const float*)d_in[17];
    const float* W23 = (const float*)d_in[18]; const float* b23 = (const float*)d_in[19];
    const float* W31 = (const float*)d_in[20]; const float* b31 = (const float*)d_in[21];
    const float* W32 = (const float*)d_in[22]; const float* b32 = (const float*)d_in[23];
    const float* W33 = (const float*)d_in[24]; const float* b33 = (const float*)d_in[25];
    const float* W2  = (const float*)d_in[26]; const float* b2  = (const float*)d_in[27];
    float* out = (float*)d_out;

    float *hc, *dense, *agg;
    int *deg, *rowstart, *cursor, *blksum, *csr;
    cudaGetSymbolAddress((void**)&hc,       g_hc);
    cudaGetSymbolAddress((void**)&dense,    g_dense);
    cudaGetSymbolAddress((void**)&agg,      g_agg);
    cudaGetSymbolAddress((void**)&deg,      g_deg);
    cudaGetSymbolAddress((void**)&rowstart, g_rowstart);
    cudaGetSymbolAddress((void**)&cursor,   g_cursor);
    cudaGetSymbolAddress((void**)&blksum,   g_blksum);
    cudaGetSymbolAddress((void**)&csr,      g_csr);

    const int EDGE_BLOCKS = (N_EDGES + 255) / 256;
    const int NVEC_BLOCKS = (N_NODES + 255) / 256;
    const int GATH_BLOCKS = (N_NODES * 32 + 255) / 256;
    const int MMA_BLOCKS  = (N_NODES + 127) / 128;   // 782

    const int L1_SMEM = F_IN * BSTRIDE * 4;          // 69632 B
    cudaFuncSetAttribute(k_layer1_mma, cudaFuncAttributeMaxDynamicSharedMemorySize,
                         L1_SMEM);

    // Side stream + events for CSR || layer-1 overlap (created once; host-side
    // resources only, no device memory).
    static cudaStream_t s2 = nullptr;
    static cudaEvent_t evRoot = nullptr, evJoin = nullptr;
    if (s2 == nullptr) {
        cudaStreamCreateWithFlags(&s2, cudaStreamNonBlocking);
        cudaEventCreateWithFlags(&evRoot, cudaEventDisableTiming);
        cudaEventCreateWithFlags(&evJoin, cudaEventDisableTiming);
    }

    // Fork: CSR build on s2, layer-1 GEMM on the main (legacy) stream.
    cudaEventRecord(evRoot, 0);
    cudaStreamWaitEvent(s2, evRoot, 0);

    k_zero_deg<<<NVEC_BLOCKS, 256, 0, s2>>>(deg);
    k_hist<<<EDGE_BLOCKS, 256, 0, s2>>>(dst, deg);
    k_scan1<<<SCAN_NBLK, SCAN_BLOCK, 0, s2>>>(deg, rowstart, blksum);
    k_scan2<<<1, 128, 0, s2>>>(blksum);
    k_scan3<<<SCAN_NBLK, SCAN_BLOCK, 0, s2>>>(rowstart, blksum, cursor);
    k_fill<<<EDGE_BLOCKS, 256, 0, s2>>>(src, dst, cursor, csr);
    cudaEventRecord(evJoin, s2);

    k_layer1_mma<<<MMA_BLOCKS, 256, L1_SMEM>>>(x, Wc1, W11, b11, W12, b12,
                                               W13, b13, hc, dense);

    // Join: gathers need both hc (main) and csr (s2).
    cudaStreamWaitEvent(0, evJoin, 0);

    k_gather<<<GATH_BLOCKS, 256>>>(csr, rowstart, deg, hc, agg);
    k_mid_mma<<<MMA_BLOCKS, 256>>>(dense, agg, bc1, Wc2, W21, b21, W22, b22,
                                   W23, b23, hc, dense);
    k_gather<<<GATH_BLOCKS, 256>>>(csr, rowstart, deg, hc, agg);
    k_mid_mma<<<MMA_BLOCKS, 256>>>(dense, agg, bc2, Wc3, W31, b31, W32, b32,
                                   W33, b33, hc, dense);
    k_gather_final<<<GATH_BLOCKS, 256>>>(csr, rowstart, deg, hc, dense, bc3, W2, b2,
                                         out);
}

// round 6
// speedup vs baseline: 1.4106x; 1.0610x over previous
#include <cuda_runtime.h>
#include <cuda_fp16.h>
#include <cstdint>

#define N_NODES 100000
#define N_EDGES 3200000
#define F_IN 128
#define NOUT 32

#define SCAN_BLOCK 1024
#define SCAN_NBLK ((N_NODES + SCAN_BLOCK - 1) / SCAN_BLOCK)   // 98

// Conflict-free smem strides: stride mod 32 == 8
#define BSTRIDE 136
#define HSTRIDE 40

// Scratch (allocation-free: __device__ globals)
__device__ __half g_hc16[N_NODES * NOUT];   // gather source (fp16)
__device__ float  g_dense[N_NODES * NOUT];
__device__ float  g_agg[N_NODES * NOUT];
__device__ int    g_deg[N_NODES];
__device__ int    g_rowstart[N_NODES + 1];  // +1 sentinel
__device__ int    g_cursor[N_NODES];
__device__ int    g_blksum[SCAN_NBLK];
__device__ int    g_csr[N_EDGES];

__device__ __forceinline__ uint32_t f2tf32(float f) {
    uint32_t r;
    asm("cvt.rna.tf32.f32 %0, %1;" : "=r"(r) : "f"(f));
    return r;
}

__device__ __forceinline__ void mma_tf32(float& d0, float& d1, float& d2, float& d3,
                                         uint32_t a0, uint32_t a1, uint32_t a2,
                                         uint32_t a3, uint32_t b0, uint32_t b1) {
    asm volatile(
        "mma.sync.aligned.m16n8k8.row.col.f32.tf32.tf32.f32 "
        "{%0,%1,%2,%3}, {%4,%5,%6,%7}, {%8,%9}, {%0,%1,%2,%3};"
        : "+f"(d0), "+f"(d1), "+f"(d2), "+f"(d3)
        : "r"(a0), "r"(a1), "r"(a2), "r"(a3), "r"(b0), "r"(b1));
}

// ===========================================================================
// CSR build: zero -> hist -> scan(3) -> fill
// ===========================================================================
__global__ void k_zero_deg(int* __restrict__ deg)
{
    int i = blockIdx.x * blockDim.x + threadIdx.x;
    if (i < N_NODES) deg[i] = 0;
}

__global__ void k_hist(const int* __restrict__ dst, int* __restrict__ deg)
{
    int e = blockIdx.x * blockDim.x + threadIdx.x;
    if (e < N_EDGES) atomicAdd(&deg[dst[e]], 1);
}

__global__ void k_scan1(const int* __restrict__ deg, int* __restrict__ rowstart,
                        int* __restrict__ blksum)
{
    __shared__ int sh[SCAN_BLOCK];
    int i = blockIdx.x * SCAN_BLOCK + threadIdx.x;
    int v = (i < N_NODES) ? deg[i] : 0;
    sh[threadIdx.x] = v;
    __syncthreads();
    for (int off = 1; off < SCAN_BLOCK; off <<= 1) {
        int t = (threadIdx.x >= off) ? sh[threadIdx.x - off] : 0;
        __syncthreads();
        sh[threadIdx.x] += t;
        __syncthreads();
    }
    if (i < N_NODES) rowstart[i] = sh[threadIdx.x] - v;
    if (threadIdx.x == SCAN_BLOCK - 1) blksum[blockIdx.x] = sh[threadIdx.x];
}

__global__ void k_scan2(int* __restrict__ blksum)
{
    __shared__ int sh[128];
    int v = (threadIdx.x < SCAN_NBLK) ? blksum[threadIdx.x] : 0;
    sh[threadIdx.x] = v;
    __syncthreads();
    for (int off = 1; off < 128; off <<= 1) {
        int t = (threadIdx.x >= off) ? sh[threadIdx.x - off] : 0;
        __syncthreads();
        sh[threadIdx.x] += t;
        __syncthreads();
    }
    if (threadIdx.x < SCAN_NBLK) blksum[threadIdx.x] = sh[threadIdx.x] - v;
}

__global__ void k_scan3(int* __restrict__ rowstart, const int* __restrict__ blksum,
                        int* __restrict__ cursor)
{
    int i = blockIdx.x * SCAN_BLOCK + threadIdx.x;
    if (i < N_NODES) {
        int r = rowstart[i] + blksum[blockIdx.x];
        rowstart[i] = r;
        cursor[i] = r;
    }
    if (i == 0) rowstart[N_NODES] = N_EDGES;   // sentinel
}

__global__ void k_fill(const int* __restrict__ src, const int* __restrict__ dst,
                       int* __restrict__ cursor, int* __restrict__ csr)
{
    int e = blockIdx.x * blockDim.x + threadIdx.x;
    if (e < N_EDGES) {
        int pos = atomicAdd(&cursor[dst[e]], 1);
        csr[pos] = src[e];
    }
}

// ===========================================================================
// Gather: warp per dst node, lane = column. fp16 source, fp32 accumulate.
// ===========================================================================
__global__ void k_gather(const int* __restrict__ csr,
                         const int* __restrict__ rowstart,
                         const __half* __restrict__ hc,
                         float* __restrict__ agg)
{
    int lane = threadIdx.x & 31;
    int node = (blockIdx.x * blockDim.x + threadIdx.x) >> 5;
    if (node >= N_NODES) return;
    int start = rowstart[node];
    int d = rowstart[node + 1] - start;
    float acc = 0.f;
    int i = 0;
    for (; i + 8 <= d; i += 8) {
        int s0 = csr[start + i + 0];
        int s1 = csr[start + i + 1];
        int s2 = csr[start + i + 2];
        int s3 = csr[start + i + 3];
        int s4 = csr[start + i + 4];
        int s5 = csr[start + i + 5];
        int s6 = csr[start + i + 6];
        int s7 = csr[start + i + 7];
        float v0 = __half2float(hc[s0 * NOUT + lane]);
        float v1 = __half2float(hc[s1 * NOUT + lane]);
        float v2 = __half2float(hc[s2 * NOUT + lane]);
        float v3 = __half2float(hc[s3 * NOUT + lane]);
        float v4 = __half2float(hc[s4 * NOUT + lane]);
        float v5 = __half2float(hc[s5 * NOUT + lane]);
        float v6 = __half2float(hc[s6 * NOUT + lane]);
        float v7 = __half2float(hc[s7 * NOUT + lane]);
        acc += ((v0 + v1) + (v2 + v3)) + ((v4 + v5) + (v6 + v7));
    }
    for (; i < d; i++)
        acc += __half2float(hc[csr[start + i] * NOUT + lane]);
    agg[node * NOUT + lane] = acc;
}

// Gather fused with final projection.
__global__ void k_gather_final(const int* __restrict__ csr,
                               const int* __restrict__ rowstart,
                               const __half* __restrict__ hc,
                               const float* __restrict__ dense_in,
                               const float* __restrict__ bc,
                               const float* __restrict__ W2,
                               const float* __restrict__ b2,
                               float* __restrict__ out)
{
    int lane = threadIdx.x & 31;
    int node = (blockIdx.x * blockDim.x + threadIdx.x) >> 5;
    if (node >= N_NODES) return;
    int start = rowstart[node];
    int d = rowstart[node + 1] - start;
    float acc = 0.f;
    int i = 0;
    for (; i + 8 <= d; i += 8) {
        int s0 = csr[start + i + 0];
        int s1 = csr[start + i + 1];
        int s2 = csr[start + i + 2];
        int s3 = csr[start + i + 3];
        int s4 = csr[start + i + 4];
        int s5 = csr[start + i + 5];
        int s6 = csr[start + i + 6];
        int s7 = csr[start + i + 7];
        float v0 = __half2float(hc[s0 * NOUT + lane]);
        float v1 = __half2float(hc[s1 * NOUT + lane]);
        float v2 = __half2float(hc[s2 * NOUT + lane]);
        float v3 = __half2float(hc[s3 * NOUT + lane]);
        float v4 = __half2float(hc[s4 * NOUT + lane]);
        float v5 = __half2float(hc[s5 * NOUT + lane]);
        float v6 = __half2float(hc[s6 * NOUT + lane]);
        float v7 = __half2float(hc[s7 * NOUT + lane]);
        acc += ((v0 + v1) + (v2 + v3)) + ((v4 + v5) + (v6 + v7));
    }
    for (; i < d; i++)
        acc += __half2float(hc[csr[start + i] * NOUT + lane]);
    float h = dense_in[node * NOUT + lane] + fmaxf(acc + bc[lane], 0.f);
    float v = h * W2[lane];
#pragma unroll
    for (int s = 16; s > 0; s >>= 1)
        v += __shfl_xor_sync(0xffffffffu, v, s);
    if (lane == 0) out[node] = v + b2[0];
}

// ===========================================================================
// Shared epilogue: hc written as fp16 pairs, dense as fp32.
// ===========================================================================
__device__ __forceinline__ void mma_epilogue(
    const float* acc, int row0, int row1, int tg,
    const float* __restrict__ ba, const float* __restrict__ bm1,
    const float* __restrict__ bm2,
    __half* __restrict__ hc, float* __restrict__ dense)
{
    bool v0 = row0 < N_NODES;
    bool v1 = row1 < N_NODES;
#pragma unroll
    for (int j = 0; j < 4; j++) {
        int nb = j * 8 + tg * 2;
        const float* aC  = acc + (j +  0) * 4;
        const float* aA  = acc + (j +  4) * 4;
        const float* aM1 = acc + (j +  8) * 4;
        const float* aM2 = acc + (j + 12) * 4;
        float ba0 = ba[nb],  ba1 = ba[nb + 1];
        float p10 = bm1[nb], p11 = bm1[nb + 1];
        float p20 = bm2[nb], p21 = bm2[nb + 1];
        if (v0) {
            *reinterpret_cast<__half2*>(hc + (size_t)row0 * NOUT + nb) =
                __floats2half2_rn(aC[0], aC[1]);
            float d0 = fmaxf(aA[0] + ba0, 0.f)
                     + fmaxf((aM1[0] + p10) * (aM2[0] + p20), 0.f);
            float d1 = fmaxf(aA[1] + ba1, 0.f)
                     + fmaxf((aM1[1] + p11) * (aM2[1] + p21), 0.f);
            *reinterpret_cast<float2*>(dense + (size_t)row0 * NOUT + nb) =
                make_float2(d0, d1);
        }
        if (v1) {
            *reinterpret_cast<__half2*>(hc + (size_t)row1 * NOUT + nb) =
                __floats2half2_rn(aC[2], aC[3]);
            float d2 = fmaxf(aA[2] + ba0, 0.f)
                     + fmaxf((aM1[2] + p10) * (aM2[2] + p20), 0.f);
            float d3 = fmaxf(aA[3] + ba1, 0.f)
                     + fmaxf((aM1[3] + p11) * (aM2[3] + p21), 0.f);
            *reinterpret_cast<float2*>(dense + (size_t)row1 * NOUT + nb) =
                make_float2(d2, d3);
        }
    }
}

// ===========================================================================
// Layer-1 GEMM via mma.sync tf32. CTA = 256 thr (8 warps) = 128 nodes.
// ===========================================================================
__global__ __launch_bounds__(256)
void k_layer1_mma(const float* __restrict__ x,
                  const float* __restrict__ Wc,
                  const float* __restrict__ Wa, const float* __restrict__ ba,
                  const float* __restrict__ Wm1, const float* __restrict__ bm1,
                  const float* __restrict__ Wm2, const float* __restrict__ bm2,
                  __half* __restrict__ hc, float* __restrict__ dense)
{
    extern __shared__ uint32_t Bs[];   // [128][BSTRIDE] tf32 bits
    const int tid = threadIdx.x;
    const float* Ws[4] = { Wc, Wa, Wm1, Wm2 };
    for (int idx = tid; idx < F_IN * 128; idx += 256) {
        int k = idx >> 7;
        int n = idx & 127;
        Bs[k * BSTRIDE + n] = f2tf32(Ws[n >> 5][k * NOUT + (n & 31)]);
    }
    __syncthreads();

    const int w = tid >> 5;
    const int lane = tid & 31;
    const int g = lane >> 2;
    const int tg = lane & 3;
    const int node0 = blockIdx.x * 128 + w * 16;
    const int row0 = node0 + g;
    const int row1 = row0 + 8;
    const float* xr0 = x + (size_t)((row0 < N_NODES) ? row0 : N_NODES - 1) * F_IN;
    const float* xr1 = x + (size_t)((row1 < N_NODES) ? row1 : N_NODES - 1) * F_IN;

    float acc[64];
#pragma unroll
    for (int i = 0; i < 64; i++) acc[i] = 0.f;

#pragma unroll
    for (int kb = 0; kb < F_IN; kb += 8) {
        uint32_t a0 = f2tf32(xr0[kb + tg]);
        uint32_t a1 = f2tf32(xr1[kb + tg]);
        uint32_t a2 = f2tf32(xr0[kb + tg + 4]);
        uint32_t a3 = f2tf32(xr1[kb + tg + 4]);
        const uint32_t* Bk0 = Bs + (kb + tg) * BSTRIDE;
        const uint32_t* Bk1 = Bs + (kb + tg + 4) * BSTRIDE;
#pragma unroll
        for (int j = 0; j < 16; j++) {
            uint32_t b0 = Bk0[j * 8 + g];
            uint32_t b1 = Bk1[j * 8 + g];
            mma_tf32(acc[j * 4 + 0], acc[j * 4 + 1], acc[j * 4 + 2], acc[j * 4 + 3],
                     a0, a1, a2, a3, b0, b1);
        }
    }

    mma_epilogue(acc, row0, row1, tg, ba, bm1, bm2, hc, dense);
}

// ===========================================================================
// K_mid GEMM via mma.sync tf32 (K=32). h staged in smem.
// ===========================================================================
__global__ __launch_bounds__(256)
void k_mid_mma(const float* __restrict__ dense_in,
               const float* __restrict__ agg_in,
               const float* __restrict__ bc_prev,
               const float* __restrict__ Wc,
               const float* __restrict__ Wa, const float* __restrict__ ba,
               const float* __restrict__ Wm1, const float* __restrict__ bm1,
               const float* __restrict__ Wm2, const float* __restrict__ bm2,
               __half* __restrict__ hc, float* __restrict__ dense_out)
{
    __shared__ uint32_t Bs[NOUT * BSTRIDE];
    __shared__ uint32_t Hs[128 * HSTRIDE];
    const int tid = threadIdx.x;
    const int node0b = blockIdx.x * 128;

    const float* Ws[4] = { Wc, Wa, Wm1, Wm2 };
    for (int idx = tid; idx < NOUT * 128; idx += 256) {
        int k = idx >> 7;
        int n = idx & 127;
        Bs[k * BSTRIDE + n] = f2tf32(Ws[n >> 5][k * NOUT + (n & 31)]);
    }
#pragma unroll
    for (int i = 0; i < 16; i++) {
        int idx = i * 256 + tid;
        int r = idx >> 5;
        int c = idx & 31;
        int node = node0b + r;
        float h = 0.f;
        if (node < N_NODES) {
            size_t o = (size_t)node * NOUT + c;
            h = dense_in[o] + fmaxf(agg_in[o] + bc_prev[c], 0.f);
        }
        Hs[r * HSTRIDE + c] = f2tf32(h);
    }
    __syncthreads();

    const int w = tid >> 5;
    const int lane = tid & 31;
    const int g = lane >> 2;
    const int tg = lane & 3;
    const int rloc0 = w * 16 + g;
    const int rloc1 = rloc0 + 8;
    const int row0 = node0b + rloc0;
    const int row1 = node0b + rloc1;

    float acc[64];
#pragma unroll
    for (int i = 0; i < 64; i++) acc[i] = 0.f;

#pragma unroll
    for (int kb = 0; kb < NOUT; kb += 8) {
        uint32_t a0 = Hs[rloc0 * HSTRIDE + kb + tg];
        uint32_t a1 = Hs[rloc1 * HSTRIDE + kb + tg];
        uint32_t a2 = Hs[rloc0 * HSTRIDE + kb + tg + 4];
        uint32_t a3 = Hs[rloc1 * HSTRIDE + kb + tg + 4];
        const uint32_t* Bk0 = Bs + (kb + tg) * BSTRIDE;
        const uint32_t* Bk1 = Bs + (kb + tg + 4) * BSTRIDE;
#pragma unroll
        for (int j = 0; j < 16; j++) {
            uint32_t b0 = Bk0[j * 8 + g];
            uint32_t b1 = Bk1[j * 8 + g];
            mma_tf32(acc[j * 4 + 0], acc[j * 4 + 1], acc[j * 4 + 2], acc[j * 4 + 3],
                     a0, a1, a2, a3, b0, b1);
        }
    }

    mma_epilogue(acc, row0, row1, tg, ba, bm1, bm2, hc, dense_out);
}

// ===========================================================================

extern "C" void kernel_launch(void* const* d_in, const int* in_sizes, int n_in,
                              void* d_out, int out_size)
{
    const float* x   = (const float*)d_in[0];
    const int* ei    = (const int*)d_in[1];
    const int* src   = ei;
    const int* dst   = ei + N_EDGES;
    const float* Wc1 = (const float*)d_in[2];  const float* bc1 = (const float*)d_in[3];
    const float* Wc2 = (const float*)d_in[4];  const float* bc2 = (const float*)d_in[5];
    const float* Wc3 = (const float*)d_in[6];  const float* bc3 = (const float*)d_in[7];
    const float* W11 = (const float*)d_in[8];  const float* b11 = (const float*)d_in[9];
    const float* W12 = (const float*)d_in[10]; const float* b12 = (const float*)d_in[11];
    const float* W13 = (const float*)d_in[12]; const float* b13 = (const float*)d_in[13];
    const float* W21 = (const float*)d_in[14]; const float* b21 = (const float*)d_in[15];
    const float* W22 = (const float*)d_in[16]; const float* b22 = (const float*)d_in[17];
    const float* W23 = (const float*)d_in[18]; const float* b23 = (const float*)d_in[19];
    const float* W31 = (const float*)d_in[20]; const float* b31 = (const float*)d_in[21];
    const float* W32 = (const float*)d_in[22]; const float* b32 = (const float*)d_in[23];
    const float* W33 = (const float*)d_in[24]; const float* b33 = (const float*)d_in[25];
    const float* W2  = (const float*)d_in[26]; const float* b2  = (const float*)d_in[27];
    float* out = (float*)d_out;

    __half* hc;
    float *dense, *agg;
    int *deg, *rowstart, *cursor, *blksum, *csr;
    cudaGetSymbolAddress((void**)&hc,       g_hc16);
    cudaGetSymbolAddress((void**)&dense,    g_dense);
    cudaGetSymbolAddress((void**)&agg,      g_agg);
    cudaGetSymbolAddress((void**)&deg,      g_deg);
    cudaGetSymbolAddress((void**)&rowstart, g_rowstart);
    cudaGetSymbolAddress((void**)&cursor,   g_cursor);
    cudaGetSymbolAddress((void**)&blksum,   g_blksum);
    cudaGetSymbolAddress((void**)&csr,      g_csr);

    const int EDGE_BLOCKS = (N_EDGES + 255) / 256;
    const int NVEC_BLOCKS = (N_NODES + 255) / 256;
    const int GATH_BLOCKS = (N_NODES * 32 + 255) / 256;
    const int MMA_BLOCKS  = (N_NODES + 127) / 128;   // 782

    const int L1_SMEM = F_IN * BSTRIDE * 4;          // 69632 B
    cudaFuncSetAttribute(k_layer1_mma, cudaFuncAttributeMaxDynamicSharedMemorySize,
                         L1_SMEM);

    // Side stream + events (created once; host-side only).
    static cudaStream_t s2 = nullptr;
    static cudaEvent_t evRoot = nullptr, evJoin = nullptr;
    if (s2 == nullptr) {
        cudaStreamCreateWithFlags(&s2, cudaStreamNonBlocking);
        cudaEventCreateWithFlags(&evRoot, cudaEventDisableTiming);
        cudaEventCreateWithFlags(&evJoin, cudaEventDisableTiming);
    }

    // Fork: CSR build on s2, layer-1 GEMM on the main stream.
    cudaEventRecord(evRoot, 0);
    cudaStreamWaitEvent(s2, evRoot, 0);

    k_zero_deg<<<NVEC_BLOCKS, 256, 0, s2>>>(deg);
    k_hist<<<EDGE_BLOCKS, 256, 0, s2>>>(dst, deg);
    k_scan1<<<SCAN_NBLK, SCAN_BLOCK, 0, s2>>>(deg, rowstart, blksum);
    k_scan2<<<1, 128, 0, s2>>>(blksum);
    k_scan3<<<SCAN_NBLK, SCAN_BLOCK, 0, s2>>>(rowstart, blksum, cursor);
    k_fill<<<EDGE_BLOCKS, 256, 0, s2>>>(src, dst, cursor, csr);
    cudaEventRecord(evJoin, s2);

    k_layer1_mma<<<MMA_BLOCKS, 256, L1_SMEM>>>(x, Wc1, W11, b11, W12, b12,
                                               W13, b13, hc, dense);

    cudaStreamWaitEvent(0, evJoin, 0);

    k_gather<<<GATH_BLOCKS, 256>>>(csr, rowstart, hc, agg);
    k_mid_mma<<<MMA_BLOCKS, 256>>>(dense, agg, bc1, Wc2, W21, b21, W22, b22,
                                   W23, b23, hc, dense);
    k_gather<<<GATH_BLOCKS, 256>>>(csr, rowstart, hc, agg);
    k_mid_mma<<<MMA_BLOCKS, 256>>>(dense, agg, bc2, Wc3, W31, b31, W32, b32,
                                   W33, b33, hc, dense);
    k_gather_final<<<GATH_BLOCKS, 256>>>(csr, rowstart, hc, dense, bc3, W2, b2,
                                         out);
}

// round 7
// speedup vs baseline: 1.5369x; 1.0896x over previous
#include <cuda_runtime.h>
#include <cuda_fp16.h>
#include <cstdint>

#define N_NODES 100000
#define N_EDGES 3200000
#define F_IN 128
#define NOUT 32

#define SCAN_BLOCK 1024
#define SCAN_NBLK ((N_NODES + SCAN_BLOCK - 1) / SCAN_BLOCK)   // 98

// Conflict-free smem strides: stride mod 32 == 8
#define BSTRIDE 136
#define HSTRIDE 40

// Scratch (allocation-free: __device__ globals)
__device__ __half g_hc16[N_NODES * NOUT];   // gather source (fp16)
__device__ float  g_dense[N_NODES * NOUT];
__device__ float  g_agg[N_NODES * NOUT];
__device__ int    g_deg[N_NODES];
__device__ int    g_rowstart[N_NODES + 1];  // +1 sentinel
__device__ int    g_cursor[N_NODES];
__device__ int    g_blksum[SCAN_NBLK];
__device__ int    g_csr[N_EDGES];

__device__ __forceinline__ uint32_t f2tf32(float f) {
    uint32_t r;
    asm("cvt.rna.tf32.f32 %0, %1;" : "=r"(r) : "f"(f));
    return r;
}

__device__ __forceinline__ void mma_tf32(float& d0, float& d1, float& d2, float& d3,
                                         uint32_t a0, uint32_t a1, uint32_t a2,
                                         uint32_t a3, uint32_t b0, uint32_t b1) {
    asm volatile(
        "mma.sync.aligned.m16n8k8.row.col.f32.tf32.tf32.f32 "
        "{%0,%1,%2,%3}, {%4,%5,%6,%7}, {%8,%9}, {%0,%1,%2,%3};"
        : "+f"(d0), "+f"(d1), "+f"(d2), "+f"(d3)
        : "r"(a0), "r"(a1), "r"(a2), "r"(a3), "r"(b0), "r"(b1));
}

// ===========================================================================
// CSR build: zero -> hist -> scan(3) -> fill
// ===========================================================================
__global__ void k_zero_deg(int* __restrict__ deg)
{
    int i = blockIdx.x * blockDim.x + threadIdx.x;
    if (i < N_NODES) deg[i] = 0;
}

__global__ void k_hist(const int* __restrict__ dst, int* __restrict__ deg)
{
    int e = blockIdx.x * blockDim.x + threadIdx.x;
    if (e < N_EDGES) atomicAdd(&deg[dst[e]], 1);
}

__global__ void k_scan1(const int* __restrict__ deg, int* __restrict__ rowstart,
                        int* __restrict__ blksum)
{
    __shared__ int sh[SCAN_BLOCK];
    int i = blockIdx.x * SCAN_BLOCK + threadIdx.x;
    int v = (i < N_NODES) ? deg[i] : 0;
    sh[threadIdx.x] = v;
    __syncthreads();
    for (int off = 1; off < SCAN_BLOCK; off <<= 1) {
        int t = (threadIdx.x >= off) ? sh[threadIdx.x - off] : 0;
        __syncthreads();
        sh[threadIdx.x] += t;
        __syncthreads();
    }
    if (i < N_NODES) rowstart[i] = sh[threadIdx.x] - v;
    if (threadIdx.x == SCAN_BLOCK - 1) blksum[blockIdx.x] = sh[threadIdx.x];
}

__global__ void k_scan2(int* __restrict__ blksum)
{
    __shared__ int sh[128];
    int v = (threadIdx.x < SCAN_NBLK) ? blksum[threadIdx.x] : 0;
    sh[threadIdx.x] = v;
    __syncthreads();
    for (int off = 1; off < 128; off <<= 1) {
        int t = (threadIdx.x >= off) ? sh[threadIdx.x - off] : 0;
        __syncthreads();
        sh[threadIdx.x] += t;
        __syncthreads();
    }
    if (threadIdx.x < SCAN_NBLK) blksum[threadIdx.x] = sh[threadIdx.x] - v;
}

__global__ void k_scan3(int* __restrict__ rowstart, const int* __restrict__ blksum,
                        int* __restrict__ cursor)
{
    int i = blockIdx.x * SCAN_BLOCK + threadIdx.x;
    if (i < N_NODES) {
        int r = rowstart[i] + blksum[blockIdx.x];
        rowstart[i] = r;
        cursor[i] = r;
    }
    if (i == 0) rowstart[N_NODES] = N_EDGES;   // sentinel
}

__global__ void k_fill(const int* __restrict__ src, const int* __restrict__ dst,
                       int* __restrict__ cursor, int* __restrict__ csr)
{
    int e = blockIdx.x * blockDim.x + threadIdx.x;
    if (e < N_EDGES) {
        int pos = atomicAdd(&cursor[dst[e]], 1);
        csr[pos] = src[e];
    }
}

// ===========================================================================
// Edge-parallel gather core: warp per node; 8 edges per LDG.128 batch
// (4 lanes/edge, each lane = 8 half columns). fp32 accumulate.
// After the loop+reduce, every lane holds the 8 column sums for column block
// (lane&3): acc[c] = agg[node][ (lane&3)*8 + c ].
// ===========================================================================
__device__ __forceinline__ void gather_core(
    const int* __restrict__ csr, const __half* __restrict__ hc,
    int start, int d, int lane, float* acc)
{
#pragma unroll
    for (int c = 0; c < 8; c++) acc[c] = 0.f;
    const int g = lane >> 2;       // edge slot in batch (0..7)
    const int j = lane & 3;        // quarter of the row (16B)
    int i = 0;
    for (; i + 8 <= d; i += 8) {
        int eid = csr[start + i + g];
        uint4 v = *reinterpret_cast<const uint4*>(
            reinterpret_cast<const char*>(hc) + ((size_t)eid << 6) + (j << 4));
        float2 f0 = __half22float2(*reinterpret_cast<__half2*>(&v.x));
        float2 f1 = __half22float2(*reinterpret_cast<__half2*>(&v.y));
        float2 f2 = __half22float2(*reinterpret_cast<__half2*>(&v.z));
        float2 f3 = __half22float2(*reinterpret_cast<__half2*>(&v.w));
        acc[0] += f0.x; acc[1] += f0.y;
        acc[2] += f1.x; acc[3] += f1.y;
        acc[4] += f2.x; acc[5] += f2.y;
        acc[6] += f3.x; acc[7] += f3.y;
    }
    int rem = d - i;
    if (g < rem) {
        int eid = csr[start + i + g];
        uint4 v = *reinterpret_cast<const uint4*>(
            reinterpret_cast<const char*>(hc) + ((size_t)eid << 6) + (j << 4));
        float2 f0 = __half22float2(*reinterpret_cast<__half2*>(&v.x));
        float2 f1 = __half22float2(*reinterpret_cast<__half2*>(&v.y));
        float2 f2 = __half22float2(*reinterpret_cast<__half2*>(&v.z));
        float2 f3 = __half22float2(*reinterpret_cast<__half2*>(&v.w));
        acc[0] += f0.x; acc[1] += f0.y;
        acc[2] += f1.x; acc[3] += f1.y;
        acc[4] += f2.x; acc[5] += f2.y;
        acc[6] += f3.x; acc[7] += f3.y;
    }
    // reduce across the 8 edge-groups (lanes with same j, stride 4)
#pragma unroll
    for (int m = 4; m <= 16; m <<= 1) {
#pragma unroll
        for (int c = 0; c < 8; c++)
            acc[c] += __shfl_xor_sync(0xffffffffu, acc[c], m);
    }
}

__global__ void k_gather(const int* __restrict__ csr,
                         const int* __restrict__ rowstart,
                         const __half* __restrict__ hc,
                         float* __restrict__ agg)
{
    int lane = threadIdx.x & 31;
    int node = (blockIdx.x * blockDim.x + threadIdx.x) >> 5;
    if (node >= N_NODES) return;
    int start = rowstart[node];
    int d = rowstart[node + 1] - start;
    float acc[8];
    gather_core(csr, hc, start, d, lane, acc);
    if (lane < 4) {
        float* ap = agg + (size_t)node * NOUT + lane * 8;
        *reinterpret_cast<float4*>(ap)     = make_float4(acc[0], acc[1], acc[2], acc[3]);
        *reinterpret_cast<float4*>(ap + 4) = make_float4(acc[4], acc[5], acc[6], acc[7]);
    }
}

// Gather fused with final projection: h = dense + relu(acc+bc); out = h@W2+b2.
__global__ void k_gather_final(const int* __restrict__ csr,
                               const int* __restrict__ rowstart,
                               const __half* __restrict__ hc,
                               const float* __restrict__ dense_in,
                               const float* __restrict__ bc,
                               const float* __restrict__ W2,
                               const float* __restrict__ b2,
                               float* __restrict__ out)
{
    int lane = threadIdx.x & 31;
    int node = (blockIdx.x * blockDim.x + threadIdx.x) >> 5;
    if (node >= N_NODES) return;
    int start = rowstart[node];
    int d = rowstart[node + 1] - start;
    float acc[8];
    gather_core(csr, hc, start, d, lane, acc);
    // lanes 0-3: partial dot over their 8 columns
    float v = 0.f;
    {
        int j = lane & 3;
        const float* dp = dense_in + (size_t)node * NOUT + j * 8;
        const float* bcp = bc + j * 8;
        const float* w2p = W2 + j * 8;
#pragma unroll
        for (int c = 0; c < 8; c++) {
            float h = dp[c] + fmaxf(acc[c] + bcp[c], 0.f);
            v = fmaf(h, w2p[c], v);
        }
    }
    v += __shfl_xor_sync(0xffffffffu, v, 1);
    v += __shfl_xor_sync(0xffffffffu, v, 2);
    if (lane == 0) out[node] = v + b2[0];
}

// ===========================================================================
// Shared epilogue: hc written as fp16 pairs, dense as fp32.
// ===========================================================================
__device__ __forceinline__ void mma_epilogue(
    const float* acc, int row0, int row1, int tg,
    const float* __restrict__ ba, const float* __restrict__ bm1,
    const float* __restrict__ bm2,
    __half* __restrict__ hc, float* __restrict__ dense)
{
    bool v0 = row0 < N_NODES;
    bool v1 = row1 < N_NODES;
#pragma unroll
    for (int j = 0; j < 4; j++) {
        int nb = j * 8 + tg * 2;
        const float* aC  = acc + (j +  0) * 4;
        const float* aA  = acc + (j +  4) * 4;
        const float* aM1 = acc + (j +  8) * 4;
        const float* aM2 = acc + (j + 12) * 4;
        float ba0 = ba[nb],  ba1 = ba[nb + 1];
        float p10 = bm1[nb], p11 = bm1[nb + 1];
        float p20 = bm2[nb], p21 = bm2[nb + 1];
        if (v0) {
            *reinterpret_cast<__half2*>(hc + (size_t)row0 * NOUT + nb) =
                __floats2half2_rn(aC[0], aC[1]);
            float d0 = fmaxf(aA[0] + ba0, 0.f)
                     + fmaxf((aM1[0] + p10) * (aM2[0] + p20), 0.f);
            float d1 = fmaxf(aA[1] + ba1, 0.f)
                     + fmaxf((aM1[1] + p11) * (aM2[1] + p21), 0.f);
            *reinterpret_cast<float2*>(dense + (size_t)row0 * NOUT + nb) =
                make_float2(d0, d1);
        }
        if (v1) {
            *reinterpret_cast<__half2*>(hc + (size_t)row1 * NOUT + nb) =
                __floats2half2_rn(aC[2], aC[3]);
            float d2 = fmaxf(aA[2] + ba0, 0.f)
                     + fmaxf((aM1[2] + p10) * (aM2[2] + p20), 0.f);
            float d3 = fmaxf(aA[3] + ba1, 0.f)
                     + fmaxf((aM1[3] + p11) * (aM2[3] + p21), 0.f);
            *reinterpret_cast<float2*>(dense + (size_t)row1 * NOUT + nb) =
                make_float2(d2, d3);
        }
    }
}

// ===========================================================================
// Layer-1 GEMM via mma.sync tf32. CTA = 256 thr (8 warps) = 128 nodes.
// ===========================================================================
__global__ __launch_bounds__(256)
void k_layer1_mma(const float* __restrict__ x,
                  const float* __restrict__ Wc,
                  const float* __restrict__ Wa, const float* __restrict__ ba,
                  const float* __restrict__ Wm1, const float* __restrict__ bm1,
                  const float* __restrict__ Wm2, const float* __restrict__ bm2,
                  __half* __restrict__ hc, float* __restrict__ dense)
{
    extern __shared__ uint32_t Bs[];   // [128][BSTRIDE] tf32 bits
    const int tid = threadIdx.x;
    const float* Ws[4] = { Wc, Wa, Wm1, Wm2 };
    for (int idx = tid; idx < F_IN * 128; idx += 256) {
        int k = idx >> 7;
        int n = idx & 127;
        Bs[k * BSTRIDE + n] = f2tf32(Ws[n >> 5][k * NOUT + (n & 31)]);
    }
    __syncthreads();

    const int w = tid >> 5;
    const int lane = tid & 31;
    const int g = lane >> 2;
    const int tg = lane & 3;
    const int node0 = blockIdx.x * 128 + w * 16;
    const int row0 = node0 + g;
    const int row1 = row0 + 8;
    const float* xr0 = x + (size_t)((row0 < N_NODES) ? row0 : N_NODES - 1) * F_IN;
    const float* xr1 = x + (size_t)((row1 < N_NODES) ? row1 : N_NODES - 1) * F_IN;

    float acc[64];
#pragma unroll
    for (int i = 0; i < 64; i++) acc[i] = 0.f;

#pragma unroll
    for (int kb = 0; kb < F_IN; kb += 8) {
        uint32_t a0 = f2tf32(xr0[kb + tg]);
        uint32_t a1 = f2tf32(xr1[kb + tg]);
        uint32_t a2 = f2tf32(xr0[kb + tg + 4]);
        uint32_t a3 = f2tf32(xr1[kb + tg + 4]);
        const uint32_t* Bk0 = Bs + (kb + tg) * BSTRIDE;
        const uint32_t* Bk1 = Bs + (kb + tg + 4) * BSTRIDE;
#pragma unroll
        for (int j = 0; j < 16; j++) {
            uint32_t b0 = Bk0[j * 8 + g];
            uint32_t b1 = Bk1[j * 8 + g];
            mma_tf32(acc[j * 4 + 0], acc[j * 4 + 1], acc[j * 4 + 2], acc[j * 4 + 3],
                     a0, a1, a2, a3, b0, b1);
        }
    }

    mma_epilogue(acc, row0, row1, tg, ba, bm1, bm2, hc, dense);
}

// ===========================================================================
// K_mid GEMM via mma.sync tf32 (K=32). h staged in smem.
// ===========================================================================
__global__ __launch_bounds__(256)
void k_mid_mma(const float* __restrict__ dense_in,
               const float* __restrict__ agg_in,
               const float* __restrict__ bc_prev,
               const float* __restrict__ Wc,
               const float* __restrict__ Wa, const float* __restrict__ ba,
               const float* __restrict__ Wm1, const float* __restrict__ bm1,
               const float* __restrict__ Wm2, const float* __restrict__ bm2,
               __half* __restrict__ hc, float* __restrict__ dense_out)
{
    __shared__ uint32_t Bs[NOUT * BSTRIDE];
    __shared__ uint32_t Hs[128 * HSTRIDE];
    const int tid = threadIdx.x;
    const int node0b = blockIdx.x * 128;

    const float* Ws[4] = { Wc, Wa, Wm1, Wm2 };
    for (int idx = tid; idx < NOUT * 128; idx += 256) {
        int k = idx >> 7;
        int n = idx & 127;
        Bs[k * BSTRIDE + n] = f2tf32(Ws[n >> 5][k * NOUT + (n & 31)]);
    }
#pragma unroll
    for (int i = 0; i < 16; i++) {
        int idx = i * 256 + tid;
        int r = idx >> 5;
        int c = idx & 31;
        int node = node0b + r;
        float h = 0.f;
        if (node < N_NODES) {
            size_t o = (size_t)node * NOUT + c;
            h = dense_in[o] + fmaxf(agg_in[o] + bc_prev[c], 0.f);
        }
        Hs[r * HSTRIDE + c] = f2tf32(h);
    }
    __syncthreads();

    const int w = tid >> 5;
    const int lane = tid & 31;
    const int g = lane >> 2;
    const int tg = lane & 3;
    const int rloc0 = w * 16 + g;
    const int rloc1 = rloc0 + 8;
    const int row0 = node0b + rloc0;
    const int row1 = node0b + rloc1;

    float acc[64];
#pragma unroll
    for (int i = 0; i < 64; i++) acc[i] = 0.f;

#pragma unroll
    for (int kb = 0; kb < NOUT; kb += 8) {
        uint32_t a0 = Hs[rloc0 * HSTRIDE + kb + tg];
        uint32_t a1 = Hs[rloc1 * HSTRIDE + kb + tg];
        uint32_t a2 = Hs[rloc0 * HSTRIDE + kb + tg + 4];
        uint32_t a3 = Hs[rloc1 * HSTRIDE + kb + tg + 4];
        const uint32_t* Bk0 = Bs + (kb + tg) * BSTRIDE;
        const uint32_t* Bk1 = Bs + (kb + tg + 4) * BSTRIDE;
#pragma unroll
        for (int j = 0; j < 16; j++) {
            uint32_t b0 = Bk0[j * 8 + g];
            uint32_t b1 = Bk1[j * 8 + g];
            mma_tf32(acc[j * 4 + 0], acc[j * 4 + 1], acc[j * 4 + 2], acc[j * 4 + 3],
                     a0, a1, a2, a3, b0, b1);
        }
    }

    mma_epilogue(acc, row0, row1, tg, ba, bm1, bm2, hc, dense_out);
}

// ===========================================================================

extern "C" void kernel_launch(void* const* d_in, const int* in_sizes, int n_in,
                              void* d_out, int out_size)
{
    const float* x   = (const float*)d_in[0];
    const int* ei    = (const int*)d_in[1];
    const int* src   = ei;
    const int* dst   = ei + N_EDGES;
    const float* Wc1 = (const float*)d_in[2];  const float* bc1 = (const float*)d_in[3];
    const float* Wc2 = (const float*)d_in[4];  const float* bc2 = (const float*)d_in[5];
    const float* Wc3 = (const float*)d_in[6];  const float* bc3 = (const float*)d_in[7];
    const float* W11 = (const float*)d_in[8];  const float* b11 = (const float*)d_in[9];
    const float* W12 = (const float*)d_in[10]; const float* b12 = (const float*)d_in[11];
    const float* W13 = (const float*)d_in[12]; const float* b13 = (const float*)d_in[13];
    const float* W21 = (const float*)d_in[14]; const float* b21 = (const float*)d_in[15];
    const float* W22 = (const float*)d_in[16]; const float* b22 = (const float*)d_in[17];
    const float* W23 = (const float*)d_in[18]; const float* b23 = (const float*)d_in[19];
    const float* W31 = (const float*)d_in[20]; const float* b31 = (const float*)d_in[21];
    const float* W32 = (const float*)d_in[22]; const float* b32 = (const float*)d_in[23];
    const float* W33 = (const float*)d_in[24]; const float* b33 = (const float*)d_in[25];
    const float* W2  = (const float*)d_in[26]; const float* b2  = (const float*)d_in[27];
    float* out = (float*)d_out;

    __half* hc;
    float *dense, *agg;
    int *deg, *rowstart, *cursor, *blksum, *csr;
    cudaGetSymbolAddress((void**)&hc,       g_hc16);
    cudaGetSymbolAddress((void**)&dense,    g_dense);
    cudaGetSymbolAddress((void**)&agg,      g_agg);
    cudaGetSymbolAddress((void**)&deg,      g_deg);
    cudaGetSymbolAddress((void**)&rowstart, g_rowstart);
    cudaGetSymbolAddress((void**)&cursor,   g_cursor);
    cudaGetSymbolAddress((void**)&blksum,   g_blksum);
    cudaGetSymbolAddress((void**)&csr,      g_csr);

    const int EDGE_BLOCKS = (N_EDGES + 255) / 256;
    const int NVEC_BLOCKS = (N_NODES + 255) / 256;
    const int GATH_BLOCKS = (N_NODES * 32 + 255) / 256;
    const int MMA_BLOCKS  = (N_NODES + 127) / 128;   // 782

    const int L1_SMEM = F_IN * BSTRIDE * 4;          // 69632 B
    cudaFuncSetAttribute(k_layer1_mma, cudaFuncAttributeMaxDynamicSharedMemorySize,
                         L1_SMEM);

    // Side stream + events (created once; host-side only).
    static cudaStream_t s2 = nullptr;
    static cudaEvent_t evRoot = nullptr, evJoin = nullptr;
    if (s2 == nullptr) {
        cudaStreamCreateWithFlags(&s2, cudaStreamNonBlocking);
        cudaEventCreateWithFlags(&evRoot, cudaEventDisableTiming);
        cudaEventCreateWithFlags(&evJoin, cudaEventDisableTiming);
    }

    // Fork: CSR build on s2, layer-1 GEMM on the main stream.
    cudaEventRecord(evRoot, 0);
    cudaStreamWaitEvent(s2, evRoot, 0);

    k_zero_deg<<<NVEC_BLOCKS, 256, 0, s2>>>(deg);
    k_hist<<<EDGE_BLOCKS, 256, 0, s2>>>(dst, deg);
    k_scan1<<<SCAN_NBLK, SCAN_BLOCK, 0, s2>>>(deg, rowstart, blksum);
    k_scan2<<<1, 128, 0, s2>>>(blksum);
    k_scan3<<<SCAN_NBLK, SCAN_BLOCK, 0, s2>>>(rowstart, blksum, cursor);
    k_fill<<<EDGE_BLOCKS, 256, 0, s2>>>(src, dst, cursor, csr);
    cudaEventRecord(evJoin, s2);

    k_layer1_mma<<<MMA_BLOCKS, 256, L1_SMEM>>>(x, Wc1, W11, b11, W12, b12,
                                               W13, b13, hc, dense);

    cudaStreamWaitEvent(0, evJoin, 0);

    k_gather<<<GATH_BLOCKS, 256>>>(csr, rowstart, hc, agg);
    k_mid_mma<<<MMA_BLOCKS, 256>>>(dense, agg, bc1, Wc2, W21, b21, W22, b22,
                                   W23, b23, hc, dense);
    k_gather<<<GATH_BLOCKS, 256>>>(csr, rowstart, hc, agg);
    k_mid_mma<<<MMA_BLOCKS, 256>>>(dense, agg, bc2, Wc3, W31, b31, W32, b32,
                                   W33, b33, hc, dense);
    k_gather_final<<<GATH_BLOCKS, 256>>>(csr, rowstart, hc, dense, bc3, W2, b2,
                                         out);
}